// round 9
// baseline (speedup 1.0000x reference)
#include <cuda_runtime.h>
#include <cuda_bf16.h>
#include <mma.h>
#include <math.h>

using namespace nvcuda;

#define BB    256
#define TS    120
#define PREDN 24
#define NJ    15
#define HH    1024
#define DD    135
#define NF    61
#define GG    3072
#define NHEAD 4
#define DHD   256

#define KP1024 1056
#define KP135  160

// ---- gemm4 smem staging ----
#define SOFF_AL 5120
#define SOFF_WH 10240
#define SOFF_WL 15360
#define SST     20480
#define SMEM_BYTES (2 * SST * 2)        // 81920 B

// ---- fused GRU kernel ----
#define NBLK_F 128                       // 2 m-tiles x 64 n-tiles
#define FA_LO  5120                      // A lo offset within stage (128x40)
#define FW_HI  10240                     // W hi (48x40)
#define FW_LO  12160
#define FSST   14080                     // bf16 per stage
#define FSMEM_BYTES (2 * FSST * 2)       // 56320 B

typedef __nv_bfloat16 bf16;

// ---------------- weight split pools ------------------------------------------
#define OFF_ATTNIN  0ull
#define OFF_WIH0    3244032ull
#define OFF_WHH0    3735552ull
#define OFF_WIH1    6979584ull
#define OFF_WHH1    10223616ull
#define OFF_FREQ    13467648ull
#define OFF_ATTNOUT 13631488ull
#define OFF_PRE     14712832ull
#define OFF_SPL1    15794176ull
#define WPOOL_TOTAL 17821696ull

__device__ bf16 g_whi[WPOOL_TOTAL];
__device__ bf16 g_wlo[WPOOL_TOTAL];

// ---------------- activation split pool ----------------------------------------
#define OFFA_IN    0ull
#define OFFA_FRQ   4915200ull
#define OFFA_FEAT  7413760ull
#define OFFA_SEQ   23904256ull
#define OFFA_OBAR  56344576ull
#define OFFA_H0    56614912ull
#define OFFA_H1    56885248ull
#define OFFA_HID   57155584ull
#define OFFA_XT    57425920ull
#define APOOL_TOTAL 57466880ull

__device__ bf16 g_ahi[APOOL_TOTAL];
__device__ bf16 g_alo[APOOL_TOTAL];

// ---------------- scratch -------------------------------------------------------
__device__ float g_big[(size_t)BB * TS * GG];
__device__ float g_seq[(size_t)BB * TS * HH];
__device__ float g_in [(size_t)BB * TS * DD];
__device__ float g_frq[(size_t)BB * NF * DD];
__device__ float g_cosm[NF * TS];
__device__ float g_obar[BB * HH];
__device__ float g_mctx[BB * HH];
__device__ float g_h0[BB * HH];
__device__ float g_h1[BB * HH];
__device__ float g_ghp[(size_t)6 * BB * GG];
__device__ float g_gxp[(size_t)6 * BB * GG];
__device__ float g_prep[(size_t)8 * BB * HH];
__device__ float g_splp[(size_t)8 * BB * NJ * 128];
__device__ float g_z1[BB * NJ * 128];
__device__ float g_p6[BB * NJ * 6];

// ---------------- software grid barrier -----------------------------------------
__device__ unsigned g_barcnt = 0;
__device__ unsigned g_barsense = 0;

__device__ __forceinline__ void grid_bar(unsigned nblk) {
    __syncthreads();
    if (threadIdx.x == 0) {
        unsigned my = *(volatile unsigned*)&g_barsense;
        __threadfence();
        unsigned arrived = atomicAdd(&g_barcnt, 1u);
        if (arrived == nblk - 1) {
            atomicExch(&g_barcnt, 0u);
            __threadfence();
            atomicExch(&g_barsense, my ^ 1u);
        } else {
            while (*(volatile unsigned*)&g_barsense == my) { }
            __threadfence();
        }
    }
    __syncthreads();
}

// ---------------- cp.async -------------------------------------------------------
__device__ __forceinline__ void cp16(bf16* dst, const bf16* src) {
    unsigned saddr = (unsigned)__cvta_generic_to_shared(dst);
    asm volatile("cp.async.cg.shared.global [%0], [%1], 16;\n" :: "r"(saddr), "l"(src));
}
#define CP_COMMIT() asm volatile("cp.async.commit_group;\n" ::: "memory")
#define CP_WAIT1()  asm volatile("cp.async.wait_group 1;\n" ::: "memory")
#define CP_WAIT0()  asm volatile("cp.async.wait_group 0;\n" ::: "memory")

// gemm4 staging: A 128x32 + W 128x32, hi/lo
__device__ __forceinline__ void stage_load(
    bf16* sb, const bf16* __restrict__ Ahi, const bf16* __restrict__ Alo,
    const bf16* __restrict__ Whi, const bf16* __restrict__ Wlo,
    int m0, int n0, int k0, int KP, int tid)
{
    #pragma unroll
    for (int it = 0; it < 2; it++) {
        int slot = tid + it * 256;
        int rw = slot >> 2;
        int col = (slot & 3) << 3;
        size_t aoff = (size_t)(m0 + rw) * KP + k0 + col;
        size_t woff = (size_t)(n0 + rw) * KP + k0 + col;
        int so = rw * 40 + col;
        cp16(sb + so,           Ahi + aoff);
        cp16(sb + SOFF_AL + so, Alo + aoff);
        cp16(sb + SOFF_WH + so, Whi + woff);
        cp16(sb + SOFF_WL + so, Wlo + woff);
    }
}

__device__ __forceinline__ void mma_stage(
    const bf16* sb, int wm, int wn,
    wmma::fragment<wmma::accumulator, 16, 16, 16, float> (&acc)[2][4])
{
    #pragma unroll
    for (int kk = 0; kk < 32; kk += 16) {
        wmma::fragment<wmma::matrix_a, 16, 16, 16, bf16, wmma::row_major> faH[2], faL[2];
        #pragma unroll
        for (int i = 0; i < 2; i++) {
            wmma::load_matrix_sync(faH[i], sb + (wm * 32 + i * 16) * 40 + kk, 40);
            wmma::load_matrix_sync(faL[i], sb + SOFF_AL + (wm * 32 + i * 16) * 40 + kk, 40);
        }
        #pragma unroll
        for (int j = 0; j < 4; j++) {
            wmma::fragment<wmma::matrix_b, 16, 16, 16, bf16, wmma::col_major> fbH, fbL;
            wmma::load_matrix_sync(fbH, sb + SOFF_WH + (wn * 64 + j * 16) * 40 + kk, 40);
            wmma::load_matrix_sync(fbL, sb + SOFF_WL + (wn * 64 + j * 16) * 40 + kk, 40);
            #pragma unroll
            for (int i = 0; i < 2; i++) {
                wmma::mma_sync(acc[i][j], faH[i], fbH, acc[i][j]);
                wmma::mma_sync(acc[i][j], faH[i], fbL, acc[i][j]);
                wmma::mma_sync(acc[i][j], faL[i], fbH, acc[i][j]);
            }
        }
    }
}

// ---------------- small utility kernels -----------------------------------------

__global__ void copy_inseq_kernel(const float* __restrict__ poses, float* __restrict__ dst) {
    int idx = blockIdx.x * 256 + threadIdx.x;
    if (idx >= BB * TS * DD) return;
    int d = idx % DD;
    int t = (idx / DD) % TS;
    int b = idx / (TS * DD);
    dst[idx] = poses[((size_t)b * (TS + PREDN) + t) * DD + d];
}

__global__ void build_cos_kernel(float* __restrict__ cosm) {
    int idx = blockIdx.x * 256 + threadIdx.x;
    if (idx >= NF * TS) return;
    int f = idx / TS, t = idx % TS;
    cosm[idx] = (float)cos(2.0 * 3.14159265358979323846 * (double)(f * t) / (double)TS);
}

__global__ void freq_kernel(const float* __restrict__ inseq, const float* __restrict__ cosm,
                            float* __restrict__ freq) {
    int b = blockIdx.x, f = blockIdx.y, d = threadIdx.x;
    if (d >= DD) return;
    const float* xp = inseq + (size_t)b * TS * DD + d;
    const float* cp = cosm + f * TS;
    float s = 0.f;
    #pragma unroll 4
    for (int t = 0; t < TS; t++) s += cp[t] * xp[(size_t)t * DD];
    freq[((size_t)b * NF + f) * DD + d] = s;
}

// ---------------- splitters -------------------------------------------------------
// perm=1: output row 3*(n%HH) + n/HH (gate-interleaved; requires N==GG)
__global__ void split_w_kernel(const float* __restrict__ W, const float* __restrict__ bias,
                               bf16* __restrict__ hi, bf16* __restrict__ lo,
                               int N, int K, int KP, int perm) {
    size_t idx = (size_t)blockIdx.x * 256 + threadIdx.x;
    if (idx >= (size_t)N * KP) return;
    int k = (int)(idx % KP);
    int n = (int)(idx / KP);
    float v = 0.f;
    if (k < K) v = W[(size_t)n * K + k];
    else if (k == K) v = bias[n];
    int outn = perm ? (3 * (n % HH) + n / HH) : n;
    size_t o = (size_t)outn * KP + k;
    bf16 h = __float2bfloat16(v);
    hi[o] = h;
    lo[o] = __float2bfloat16(v - __bfloat162float(h));
}

__global__ void split_a_kernel(const float* __restrict__ A,
                               bf16* __restrict__ hi, bf16* __restrict__ lo,
                               int M, int K, int KP) {
    size_t idx = (size_t)blockIdx.x * 256 + threadIdx.x;
    if (idx >= (size_t)M * KP) return;
    int k = (int)(idx % KP);
    int m = (int)(idx / KP);
    float v = 0.f;
    if (k < K) v = A[(size_t)m * K + k];
    else if (k == K) v = 1.0f;
    bf16 h = __float2bfloat16(v);
    hi[idx] = h;
    lo[idx] = __float2bfloat16(v - __bfloat162float(h));
}

__global__ void zero_split_kernel(bf16* __restrict__ hi, bf16* __restrict__ lo,
                                  int M, int K, int KP) {
    size_t idx = (size_t)blockIdx.x * 256 + threadIdx.x;
    if (idx >= (size_t)M * KP) return;
    int k = (int)(idx % KP);
    float v = (k == K) ? 1.0f : 0.0f;
    hi[idx] = __float2bfloat16(v);
    lo[idx] = __float2bfloat16(0.0f);
}

// ---------------- gemm4 (batch / decode) -------------------------------------------
__global__ __launch_bounds__(256, 2) void gemm4_kernel(
    const bf16* __restrict__ Ahi, const bf16* __restrict__ Alo,
    const bf16* __restrict__ Whi, const bf16* __restrict__ Wlo,
    float* __restrict__ C, int M, int N, int KP)
{
    extern __shared__ __align__(16) bf16 sm4[];
    int tid = threadIdx.x;
    int warp = tid >> 5;
    int wm = warp >> 1, wn = warp & 1;
    int m0 = blockIdx.y * 128, n0 = blockIdx.x * 128;

    wmma::fragment<wmma::accumulator, 16, 16, 16, float> acc[2][4];
    #pragma unroll
    for (int i = 0; i < 2; i++)
        #pragma unroll
        for (int j = 0; j < 4; j++)
            wmma::fill_fragment(acc[i][j], 0.0f);

    int CH  = KP >> 5;
    int cpz = (CH + gridDim.z - 1) / gridDim.z;
    int c0  = blockIdx.z * cpz;
    int c1  = c0 + cpz; if (c1 > CH) c1 = CH;
    int nch = c1 - c0;

    if (nch > 0) {
        stage_load(sm4, Ahi, Alo, Whi, Wlo, m0, n0, c0 << 5, KP, tid);
        CP_COMMIT();
    }
    for (int i = 0; i < nch; i++) {
        bf16* sb = sm4 + (i & 1) * SST;
        if (i + 1 < nch) {
            stage_load(sm4 + ((i + 1) & 1) * SST, Ahi, Alo, Whi, Wlo,
                       m0, n0, (c0 + i + 1) << 5, KP, tid);
            CP_COMMIT();
            CP_WAIT1();
        } else {
            CP_WAIT0();
        }
        __syncthreads();
        mma_stage(sb, wm, wn, acc);
        __syncthreads();
    }

    float* Cz = C + (size_t)blockIdx.z * M * N;
    #pragma unroll
    for (int i = 0; i < 2; i++)
        #pragma unroll
        for (int j = 0; j < 4; j++)
            wmma::store_matrix_sync(
                Cz + (size_t)(m0 + wm * 32 + i * 16) * N + (n0 + wn * 64 + j * 16),
                acc[i][j], N, wmma::mem_row_major);
}

// ---------------- fused persistent GRU recurrence --------------------------------
// 128 CTAs: tile 128(m) x 48(permuted n) = 16 gate triples. Full K per CTA,
// gate computed in-epilogue, h/hhi/hlo/seq written by the owning CTA.
// ONE grid barrier per step.
__global__ __launch_bounds__(256, 1) void gru_fused_kernel(
    const float* __restrict__ gi,          // (B, TS, GG) PERMUTED cols, bih fused
    const bf16* __restrict__ Whi,          // (GG perm rows, KP1024), bhh col HH
    const bf16* __restrict__ Wlo,
    float* __restrict__ h,                 // (B, HH) fp32
    bf16* __restrict__ hhi,                // (B, KP1024)
    bf16* __restrict__ hlo,
    bf16* __restrict__ seqhi,              // (B, TS, KP1024) or null
    bf16* __restrict__ seqlo,
    int nsteps)
{
    extern __shared__ __align__(16) bf16 sm4[];
    float* ghs = (float*)sm4;              // 128x48 fp32 (aliases stage area)
    int tid = threadIdx.x;
    int warp = tid >> 5;                   // 0..7, owns rows warp*16..+15
    int tm = blockIdx.x & 1;
    int tn = blockIdx.x >> 1;              // 0..63
    int m0 = tm * 128;
    int n0p = tn * 48;                     // permuted col base
    int j0 = tn * 16;                      // hidden-unit base

    for (int t = 0; t < nsteps; t++) {
        wmma::fragment<wmma::accumulator, 16, 16, 16, float> acc[3];
        #pragma unroll
        for (int j = 0; j < 3; j++) wmma::fill_fragment(acc[j], 0.0f);

        // prefetch chunk 0
        {
            bf16* sb = sm4;
            #pragma unroll
            for (int it = 0; it < 2; it++) {
                int slot = tid + it * 256;
                int rw = slot >> 2;
                int col = (slot & 3) << 3;
                size_t aoff = (size_t)(m0 + rw) * KP1024 + col;
                int so = rw * 40 + col;
                cp16(sb + so,         hhi + aoff);
                cp16(sb + FA_LO + so, hlo + aoff);
            }
            if (tid < 192) {
                int rw = tid >> 2;
                int col = (tid & 3) << 3;
                size_t woff = (size_t)(n0p + rw) * KP1024 + col;
                int so = rw * 40 + col;
                cp16(sb + FW_HI + so, Whi + woff);
                cp16(sb + FW_LO + so, Wlo + woff);
            }
            CP_COMMIT();
        }

        for (int c = 0; c < 33; c++) {
            bf16* sb = sm4 + (c & 1) * FSST;
            if (c + 1 < 33) {
                bf16* nb = sm4 + ((c + 1) & 1) * FSST;
                int k0 = (c + 1) << 5;
                #pragma unroll
                for (int it = 0; it < 2; it++) {
                    int slot = tid + it * 256;
                    int rw = slot >> 2;
                    int col = (slot & 3) << 3;
                    size_t aoff = (size_t)(m0 + rw) * KP1024 + k0 + col;
                    int so = rw * 40 + col;
                    cp16(nb + so,         hhi + aoff);
                    cp16(nb + FA_LO + so, hlo + aoff);
                }
                if (tid < 192) {
                    int rw = tid >> 2;
                    int col = (tid & 3) << 3;
                    size_t woff = (size_t)(n0p + rw) * KP1024 + k0 + col;
                    int so = rw * 40 + col;
                    cp16(nb + FW_HI + so, Whi + woff);
                    cp16(nb + FW_LO + so, Wlo + woff);
                }
                CP_COMMIT();
                CP_WAIT1();
            } else {
                CP_WAIT0();
            }
            __syncthreads();
            #pragma unroll
            for (int kk = 0; kk < 32; kk += 16) {
                wmma::fragment<wmma::matrix_a, 16, 16, 16, bf16, wmma::row_major> faH, faL;
                wmma::load_matrix_sync(faH, sb + (warp * 16) * 40 + kk, 40);
                wmma::load_matrix_sync(faL, sb + FA_LO + (warp * 16) * 40 + kk, 40);
                #pragma unroll
                for (int j = 0; j < 3; j++) {
                    wmma::fragment<wmma::matrix_b, 16, 16, 16, bf16, wmma::col_major> fbH, fbL;
                    wmma::load_matrix_sync(fbH, sb + FW_HI + (j * 16) * 40 + kk, 40);
                    wmma::load_matrix_sync(fbL, sb + FW_LO + (j * 16) * 40 + kk, 40);
                    wmma::mma_sync(acc[j], faH, fbH, acc[j]);
                    wmma::mma_sync(acc[j], faH, fbL, acc[j]);
                    wmma::mma_sync(acc[j], faL, fbH, acc[j]);
                }
            }
            __syncthreads();
        }

        // epilogue: acc -> smem gh (128x48), then gate math
        #pragma unroll
        for (int j = 0; j < 3; j++)
            wmma::store_matrix_sync(ghs + (warp * 16) * 48 + j * 16, acc[j], 48,
                                    wmma::mem_row_major);
        __syncthreads();

        #pragma unroll
        for (int it = 0; it < 8; it++) {
            int cell = tid + it * 256;          // 0..2047
            int row = cell >> 4;                // 0..127
            int jl  = cell & 15;                // 0..15
            int b = m0 + row;
            int j = j0 + jl;
            const float* gib = gi + ((size_t)b * TS + t) * GG + 3 * (size_t)j;
            float hr = ghs[row * 48 + jl * 3 + 0];
            float hz = ghs[row * 48 + jl * 3 + 1];
            float hn = ghs[row * 48 + jl * 3 + 2];
            float r = 1.f / (1.f + expf(-(gib[0] + hr)));
            float z = 1.f / (1.f + expf(-(gib[1] + hz)));
            float n = tanhf(gib[2] + r * hn);
            float hp = h[(size_t)b * HH + j];
            float hnew = (1.f - z) * n + z * hp;
            h[(size_t)b * HH + j] = hnew;
            bf16 hb = __float2bfloat16(hnew);
            bf16 lb = __float2bfloat16(hnew - __bfloat162float(hb));
            size_t ho = (size_t)b * KP1024 + j;
            hhi[ho] = hb;
            hlo[ho] = lb;
            if (seqhi) {
                size_t so = ((size_t)b * TS + t) * KP1024 + j;
                seqhi[so] = hb;
                seqlo[so] = lb;
            }
        }
        __threadfence();
        grid_bar(NBLK_F);
    }
}

// ---------------- attention --------------------------------------------------------
__global__ __launch_bounds__(256) void attention_kernel(const float* __restrict__ qkv,
                                                        float* __restrict__ o) {
    extern __shared__ float sm[];
    float* kv = sm;
    float* sc = sm + NF * DHD;
    int b = blockIdx.x >> 2;
    int h = blockIdx.x & 3;
    int tid = threadIdx.x;
    int lane = tid & 31, w = tid >> 5;
    const float* base = qkv + (size_t)b * NF * GG + h * DHD;

    for (int idx = tid; idx < NF * DHD; idx += 256) {
        int t = idx >> 8, d = idx & 255;
        kv[idx] = base[(size_t)t * GG + HH + d];
    }
    __syncthreads();
    for (int i = w; i < NF; i += 8) {
        float q[8];
        const float* qp = base + (size_t)i * GG;
        #pragma unroll
        for (int c = 0; c < 8; c++) q[c] = qp[lane + 32 * c];
        for (int j = 0; j < NF; j++) {
            const float* kp = kv + j * DHD;
            float s = 0.f;
            #pragma unroll
            for (int c = 0; c < 8; c++) s += q[c] * kp[lane + 32 * c];
            #pragma unroll
            for (int off = 16; off; off >>= 1) s += __shfl_xor_sync(0xffffffffu, s, off);
            if (lane == 0) sc[i * 64 + j] = s * 0.0625f;
        }
    }
    __syncthreads();
    for (int i = w; i < NF; i += 8) {
        float v0 = (lane < NF) ? sc[i * 64 + lane] : -1e30f;
        float v1 = (lane + 32 < NF) ? sc[i * 64 + lane + 32] : -1e30f;
        float m = fmaxf(v0, v1);
        #pragma unroll
        for (int off = 16; off; off >>= 1) m = fmaxf(m, __shfl_xor_sync(0xffffffffu, m, off));
        float e0 = (lane < NF) ? expf(v0 - m) : 0.f;
        float e1 = (lane + 32 < NF) ? expf(v1 - m) : 0.f;
        float ss = e0 + e1;
        #pragma unroll
        for (int off = 16; off; off >>= 1) ss += __shfl_xor_sync(0xffffffffu, ss, off);
        float inv = 1.f / ss;
        if (lane < NF) sc[i * 64 + lane] = e0 * inv;
        if (lane + 32 < NF) sc[i * 64 + lane + 32] = e1 * inv;
    }
    __syncthreads();
    for (int idx = tid; idx < NF * DHD; idx += 256) {
        int t = idx >> 8, d = idx & 255;
        kv[idx] = base[(size_t)t * GG + 2 * HH + d];
    }
    __syncthreads();
    float acc[NF];
    #pragma unroll
    for (int i = 0; i < NF; i++) acc[i] = 0.f;
    int d = tid;
    for (int j = 0; j < NF; j++) {
        float vv = kv[j * DHD + d];
        #pragma unroll
        for (int i = 0; i < NF; i++) acc[i] += sc[i * 64 + j] * vv;
    }
    float* ob = o + (size_t)b * NF * HH + h * DHD + d;
    #pragma unroll
    for (int i = 0; i < NF; i++) ob[(size_t)i * HH] = acc[i];
}

__global__ void mean61_kernel(const float* __restrict__ o, float* __restrict__ obar) {
    int idx = blockIdx.x * 256 + threadIdx.x;
    if (idx >= BB * HH) return;
    int b = idx >> 10, c = idx & 1023;
    const float* p = o + (size_t)b * NF * HH + c;
    float s = 0.f;
    for (int t = 0; t < NF; t++) s += p[(size_t)t * HH];
    obar[idx] = s * (1.f / (float)NF);
}

// ---------------- decode gate (PERMUTED gate columns) ------------------------------
__global__ void gru_gate2(const float* __restrict__ gxp, int gx_sk,
                          const float* __restrict__ ghp, int gh_sk,
                          float* __restrict__ h,
                          bf16* __restrict__ hhi, bf16* __restrict__ hlo) {
    int idx = blockIdx.x * 256 + threadIdx.x;
    if (idx >= BB * HH) return;
    int b = idx >> 10, j = idx & 1023;
    float ir = 0.f, iz = 0.f, in = 0.f;
    for (int s = 0; s < gx_sk; s++) {
        const float* g = gxp + (size_t)s * (BB * GG) + (size_t)b * GG + 3 * (size_t)j;
        ir += g[0]; iz += g[1]; in += g[2];
    }
    float hr = 0.f, hz = 0.f, hn = 0.f;
    for (int s = 0; s < gh_sk; s++) {
        const float* g = ghp + (size_t)s * (BB * GG) + (size_t)b * GG + 3 * (size_t)j;
        hr += g[0]; hz += g[1]; hn += g[2];
    }
    float r = 1.f / (1.f + expf(-(ir + hr)));
    float z = 1.f / (1.f + expf(-(iz + hz)));
    float n = tanhf(in + r * hn);
    float hp = h[idx];
    float hnew = (1.f - z) * n + z * hp;
    h[idx] = hnew;
    bf16 hb = __float2bfloat16(hnew);
    size_t ho = (size_t)b * KP1024 + j;
    hhi[ho] = hb;
    hlo[ho] = __float2bfloat16(hnew - __bfloat162float(hb));
}

// ---------------- split-K reductions ------------------------------------------------
__global__ void reduce_act_kernel(const float* __restrict__ part, int sk, int mn,
                                  float* __restrict__ out) {
    int idx = blockIdx.x * 256 + threadIdx.x;
    if (idx >= mn) return;
    float s = 0.f;
    for (int i = 0; i < sk; i++) s += part[(size_t)i * mn + idx];
    out[idx] = fmaxf(s, 0.f);
}

__global__ void reduce_split_kernel(const float* __restrict__ part, int sk,
                                    const float* __restrict__ addend,
                                    bf16* __restrict__ hi, bf16* __restrict__ lo) {
    int idx = blockIdx.x * 256 + threadIdx.x;
    if (idx >= BB * HH) return;
    int b = idx >> 10, j = idx & 1023;
    float s = 0.f;
    for (int i = 0; i < sk; i++) s += part[(size_t)i * (BB * HH) + idx];
    s = fmaxf(s, 0.f) + addend[idx];
    bf16 hb = __float2bfloat16(s);
    size_t o = (size_t)b * KP1024 + j;
    hi[o] = hb;
    lo[o] = __float2bfloat16(s - __bfloat162float(hb));
}

// ---------------- decode init ---------------------------------------------------------
__global__ void init_decode(const float* __restrict__ inseq,
                            bf16* __restrict__ xthi, bf16* __restrict__ xtlo,
                            float* __restrict__ p6) {
    int idx = blockIdx.x * 256 + threadIdx.x;
    if (idx >= BB * KP135) return;
    int b = idx / KP135, d = idx % KP135;
    const float* last = inseq + ((size_t)b * TS + (TS - 1)) * DD;
    float v = 0.f;
    if (d < DD) v = last[d];
    else if (d == DD) v = 1.0f;
    bf16 hb = __float2bfloat16(v);
    xthi[idx] = hb;
    xtlo[idx] = __float2bfloat16(v - __bfloat162float(hb));
    if (d < NJ * 6) {
        int j = d / 6, o = d % 6;
        int src = (o < 3) ? (j * 9 + o * 3) : (j * 9 + (o - 3) * 3 + 1);
        p6[(size_t)b * 90 + d] = last[src];
    }
}

// ---------------- spl head layer2 + rot6d -------------------------------------------
__global__ __launch_bounds__(192) void spl2_rot(const float* __restrict__ z1,
                                                const float* __restrict__ w2,
                                                const float* __restrict__ b2,
                                                float* __restrict__ p6,
                                                bf16* __restrict__ xthi,
                                                bf16* __restrict__ xtlo,
                                                float* __restrict__ out, int step) {
    int bj = blockIdx.x;
    int b = bj / NJ, j = bj % NJ;
    int w = threadIdx.x >> 5, lane = threadIdx.x & 31;
    __shared__ float v6[6];
    const float* zz = z1 + (size_t)b * (NJ * 128) + j * 128;
    const float* ww = w2 + ((size_t)j * 6 + w) * 128;
    float s = 0.f;
    #pragma unroll
    for (int c = 0; c < 4; c++) s += zz[lane + 32 * c] * ww[lane + 32 * c];
    #pragma unroll
    for (int off = 16; off; off >>= 1) s += __shfl_xor_sync(0xffffffffu, s, off);
    if (lane == 0)
        v6[w] = p6[(size_t)b * 90 + j * 6 + w] + s + b2[j * 6 + w];
    __syncthreads();
    if (threadIdx.x < 6) {
        float v = v6[threadIdx.x];
        p6[(size_t)b * 90 + j * 6 + threadIdx.x] = v;
        out[((size_t)b * PREDN + step) * 90 + j * 6 + threadIdx.x] = v;
    }
    if (threadIdx.x == 0) {
        float a1x = v6[0], a2x = v6[1], a1y = v6[2], a2y = v6[3], a1z = v6[4], a2z = v6[5];
        float n1 = fmaxf(sqrtf(a1x*a1x + a1y*a1y + a1z*a1z), 1e-12f);
        float b1x = a1x / n1, b1y = a1y / n1, b1z = a1z / n1;
        float dot = b1x*a2x + b1y*a2y + b1z*a2z;
        float ox = a2x - dot*b1x, oy = a2y - dot*b1y, oz = a2z - dot*b1z;
        float n2 = fmaxf(sqrtf(ox*ox + oy*oy + oz*oz), 1e-12f);
        float b2x = ox / n2, b2y = oy / n2, b2z = oz / n2;
        float b3x = b1y*b2z - b1z*b2y;
        float b3y = b1z*b2x - b1x*b2z;
        float b3z = b1x*b2y - b1y*b2x;
        float rm[9] = { b1x, b2x, b3x, b1y, b2y, b3y, b1z, b2z, b3z };
        size_t base = (size_t)b * KP135 + j * 9;
        #pragma unroll
        for (int c = 0; c < 9; c++) {
            bf16 hb = __float2bfloat16(rm[c]);
            xthi[base + c] = hb;
            xtlo[base + c] = __float2bfloat16(rm[c] - __bfloat162float(hb));
        }
    }
}

// ---------------- host orchestration --------------------------------------------------

static inline void gemm4(const bf16* ahi, const bf16* alo,
                         const bf16* whi, const bf16* wlo,
                         float* C, int M, int N, int KP, int sk) {
    dim3 g(N / 128, M / 128, sk);
    gemm4_kernel<<<g, 256, SMEM_BYTES>>>(ahi, alo, whi, wlo, C, M, N, KP);
}

static inline void splitw(const float* W, const float* bias,
                          bf16* hi, bf16* lo, int N, int K, int KP, int perm) {
    size_t n = (size_t)N * KP;
    split_w_kernel<<<(int)((n + 255) / 256), 256>>>(W, bias, hi, lo, N, K, KP, perm);
}

static inline void splita(const float* A, bf16* hi, bf16* lo, int M, int K, int KP) {
    size_t n = (size_t)M * KP;
    split_a_kernel<<<(int)((n + 255) / 256), 256>>>(A, hi, lo, M, K, KP);
}

static inline void zerosplit(bf16* hi, bf16* lo, int M, int K, int KP) {
    size_t n = (size_t)M * KP;
    zero_split_kernel<<<(int)((n + 255) / 256), 256>>>(hi, lo, M, K, KP);
}

extern "C" void kernel_launch(void* const* d_in, const int* in_sizes, int n_in,
                              void* d_out, int out_size) {
    const float* poses      = (const float*)d_in[0];
    const float* freq_w     = (const float*)d_in[1];
    const float* freq_b     = (const float*)d_in[2];
    const float* attn_in_w  = (const float*)d_in[3];
    const float* attn_in_b  = (const float*)d_in[4];
    const float* attn_out_w = (const float*)d_in[5];
    const float* attn_out_b = (const float*)d_in[6];
    const float* gru_wih0   = (const float*)d_in[7];
    const float* gru_whh0   = (const float*)d_in[8];
    const float* gru_bih0   = (const float*)d_in[9];
    const float* gru_bhh0   = (const float*)d_in[10];
    const float* gru_wih1   = (const float*)d_in[11];
    const float* gru_whh1   = (const float*)d_in[12];
    const float* gru_bih1   = (const float*)d_in[13];
    const float* gru_bhh1   = (const float*)d_in[14];
    const float* pre_w      = (const float*)d_in[15];
    const float* pre_b      = (const float*)d_in[16];
    const float* spl_w1     = (const float*)d_in[17];
    const float* spl_b1     = (const float*)d_in[18];
    const float* spl_w2     = (const float*)d_in[19];
    const float* spl_b2     = (const float*)d_in[20];
    float* out = (float*)d_out;

    float *pBig, *pSeq, *pIn, *pFrq, *pCos, *pObar, *pMctx, *pH0, *pH1,
          *pGhp, *pGxp, *pPrep, *pSplp, *pZ1, *pP6;
    bf16 *pWhi, *pWlo, *pAhi, *pAlo;
    cudaGetSymbolAddress((void**)&pBig, g_big);
    cudaGetSymbolAddress((void**)&pSeq, g_seq);
    cudaGetSymbolAddress((void**)&pIn,  g_in);
    cudaGetSymbolAddress((void**)&pFrq, g_frq);
    cudaGetSymbolAddress((void**)&pCos, g_cosm);
    cudaGetSymbolAddress((void**)&pObar, g_obar);
    cudaGetSymbolAddress((void**)&pMctx, g_mctx);
    cudaGetSymbolAddress((void**)&pH0, g_h0);
    cudaGetSymbolAddress((void**)&pH1, g_h1);
    cudaGetSymbolAddress((void**)&pGhp, g_ghp);
    cudaGetSymbolAddress((void**)&pGxp, g_gxp);
    cudaGetSymbolAddress((void**)&pPrep, g_prep);
    cudaGetSymbolAddress((void**)&pSplp, g_splp);
    cudaGetSymbolAddress((void**)&pZ1, g_z1);
    cudaGetSymbolAddress((void**)&pP6, g_p6);
    cudaGetSymbolAddress((void**)&pWhi, g_whi);
    cudaGetSymbolAddress((void**)&pWlo, g_wlo);
    cudaGetSymbolAddress((void**)&pAhi, g_ahi);
    cudaGetSymbolAddress((void**)&pAlo, g_alo);

    cudaFuncSetAttribute(gemm4_kernel, cudaFuncAttributeMaxDynamicSharedMemorySize, SMEM_BYTES);
    cudaFuncSetAttribute(gru_fused_kernel, cudaFuncAttributeMaxDynamicSharedMemorySize, FSMEM_BYTES);

    float* qkv   = pBig;
    float* attno = pBig + (size_t)BB * NF * GG;
    float* gi    = pBig;
    float* feat  = pSeq;

    const int BF = BB * NF;
    const int BT = BB * TS;

    // ---- one-time weight splits (GRU weights gate-permuted) ----
    splitw(attn_in_w, attn_in_b, pWhi + OFF_ATTNIN,  pWlo + OFF_ATTNIN,  GG, HH, KP1024, 0);
    splitw(gru_wih0,  gru_bih0,  pWhi + OFF_WIH0,    pWlo + OFF_WIH0,    GG, DD, KP135, 1);
    splitw(gru_whh0,  gru_bhh0,  pWhi + OFF_WHH0,    pWlo + OFF_WHH0,    GG, HH, KP1024, 1);
    splitw(gru_wih1,  gru_bih1,  pWhi + OFF_WIH1,    pWlo + OFF_WIH1,    GG, HH, KP1024, 1);
    splitw(gru_whh1,  gru_bhh1,  pWhi + OFF_WHH1,    pWlo + OFF_WHH1,    GG, HH, KP1024, 1);
    splitw(freq_w,    freq_b,    pWhi + OFF_FREQ,    pWlo + OFF_FREQ,    HH, DD, KP135, 0);
    splitw(attn_out_w,attn_out_b,pWhi + OFF_ATTNOUT, pWlo + OFF_ATTNOUT, HH, HH, KP1024, 0);
    splitw(pre_w,     pre_b,     pWhi + OFF_PRE,     pWlo + OFF_PRE,     HH, HH, KP1024, 0);
    splitw(spl_w1,    spl_b1,    pWhi + OFF_SPL1,    pWlo + OFF_SPL1,    NJ*128, HH, KP1024, 0);

    // ---- activation split buffer init ----
    zerosplit(pAhi + OFFA_SEQ, pAlo + OFFA_SEQ, BT, HH, KP1024);
    zerosplit(pAhi + OFFA_H0,  pAlo + OFFA_H0,  BB, HH, KP1024);
    zerosplit(pAhi + OFFA_H1,  pAlo + OFFA_H1,  BB, HH, KP1024);
    zerosplit(pAhi + OFFA_HID, pAlo + OFFA_HID, BB, HH, KP1024);

    // ---- frequency attention branch ----
    copy_inseq_kernel<<<(BB*TS*DD + 255) / 256, 256>>>(poses, pIn);
    build_cos_kernel<<<(NF*TS + 255) / 256, 256>>>(pCos);
    freq_kernel<<<dim3(BB, NF), 160>>>(pIn, pCos, pFrq);
    splita(pFrq, pAhi + OFFA_FRQ, pAlo + OFFA_FRQ, BF, DD, KP135);
    gemm4(pAhi + OFFA_FRQ, pAlo + OFFA_FRQ, pWhi + OFF_FREQ, pWlo + OFF_FREQ,
          feat, BF, HH, KP135, 1);
    splita(feat, pAhi + OFFA_FEAT, pAlo + OFFA_FEAT, BF, HH, KP1024);
    gemm4(pAhi + OFFA_FEAT, pAlo + OFFA_FEAT, pWhi + OFF_ATTNIN, pWlo + OFF_ATTNIN,
          qkv, BF, GG, KP1024, 1);

    int smem_attn = (NF * DHD + NF * 64) * (int)sizeof(float);
    cudaFuncSetAttribute(attention_kernel, cudaFuncAttributeMaxDynamicSharedMemorySize, smem_attn);
    attention_kernel<<<BB * NHEAD, 256, smem_attn>>>(qkv, attno);
    mean61_kernel<<<(BB*HH + 255) / 256, 256>>>(attno, pObar);
    splita(pObar, pAhi + OFFA_OBAR, pAlo + OFFA_OBAR, BB, HH, KP1024);
    gemm4(pAhi + OFFA_OBAR, pAlo + OFFA_OBAR, pWhi + OFF_ATTNOUT, pWlo + OFF_ATTNOUT,
          pMctx, BB, HH, KP1024, 1);

    // ---- GRU layer 0 (fused persistent recurrence) ----
    splita(pIn, pAhi + OFFA_IN, pAlo + OFFA_IN, BT, DD, KP135);
    gemm4(pAhi + OFFA_IN, pAlo + OFFA_IN, pWhi + OFF_WIH0, pWlo + OFF_WIH0,
          gi, BT, GG, KP135, 1);
    cudaMemsetAsync(pH0, 0, (size_t)BB * HH * sizeof(float));
    gru_fused_kernel<<<NBLK_F, 256, FSMEM_BYTES>>>(gi, pWhi + OFF_WHH0, pWlo + OFF_WHH0,
                                      pH0, pAhi + OFFA_H0, pAlo + OFFA_H0,
                                      pAhi + OFFA_SEQ, pAlo + OFFA_SEQ, TS);

    // ---- GRU layer 1 ----
    gemm4(pAhi + OFFA_SEQ, pAlo + OFFA_SEQ, pWhi + OFF_WIH1, pWlo + OFF_WIH1,
          gi, BT, GG, KP1024, 1);
    cudaMemsetAsync(pH1, 0, (size_t)BB * HH * sizeof(float));
    gru_fused_kernel<<<NBLK_F, 256, FSMEM_BYTES>>>(gi, pWhi + OFF_WHH1, pWlo + OFF_WHH1,
                                      pH1, pAhi + OFFA_H1, pAlo + OFFA_H1,
                                      nullptr, nullptr, TS);

    // ---- autoregressive decode ----
    init_decode<<<(BB*KP135 + 255) / 256, 256>>>(pIn, pAhi + OFFA_XT, pAlo + OFFA_XT, pP6);
    for (int s = 0; s < PREDN; s++) {
        gemm4(pAhi + OFFA_XT, pAlo + OFFA_XT, pWhi + OFF_WIH0, pWlo + OFF_WIH0,
              pGxp, BB, GG, KP135, 2);
        gemm4(pAhi + OFFA_H0, pAlo + OFFA_H0, pWhi + OFF_WHH0, pWlo + OFF_WHH0,
              pGhp, BB, GG, KP1024, 6);
        gru_gate2<<<(BB*HH)/256, 256>>>(pGxp, 2, pGhp, 6, pH0,
                                        pAhi + OFFA_H0, pAlo + OFFA_H0);

        gemm4(pAhi + OFFA_H0, pAlo + OFFA_H0, pWhi + OFF_WIH1, pWlo + OFF_WIH1,
              pGxp, BB, GG, KP1024, 6);
        gemm4(pAhi + OFFA_H1, pAlo + OFFA_H1, pWhi + OFF_WHH1, pWlo + OFF_WHH1,
              pGhp, BB, GG, KP1024, 6);
        gru_gate2<<<(BB*HH)/256, 256>>>(pGxp, 6, pGhp, 6, pH1,
                                        pAhi + OFFA_H1, pAlo + OFFA_H1);

        gemm4(pAhi + OFFA_H1, pAlo + OFFA_H1, pWhi + OFF_PRE, pWlo + OFF_PRE,
              pPrep, BB, HH, KP1024, 8);
        reduce_split_kernel<<<(BB*HH + 255)/256, 256>>>(pPrep, 8, pMctx,
                                                        pAhi + OFFA_HID, pAlo + OFFA_HID);

        gemm4(pAhi + OFFA_HID, pAlo + OFFA_HID, pWhi + OFF_SPL1, pWlo + OFF_SPL1,
              pSplp, BB, NJ*128, KP1024, 8);
        reduce_act_kernel<<<(BB*NJ*128 + 255)/256, 256>>>(pSplp, 8, BB*NJ*128, pZ1);

        spl2_rot<<<BB * NJ, 192>>>(pZ1, spl_w2, spl_b2, pP6,
                                   pAhi + OFFA_XT, pAlo + OFFA_XT, out, s);
    }
}

// round 10
// speedup vs baseline: 1.0824x; 1.0824x over previous
#include <cuda_runtime.h>
#include <cuda_bf16.h>
#include <mma.h>
#include <math.h>

using namespace nvcuda;

#define BB    256
#define TS    120
#define PREDN 24
#define NJ    15
#define HH    1024
#define DD    135
#define NF    61
#define GG    3072
#define NHEAD 4
#define DHD   256

#define KP1024 1056
#define KP135  160

#define NBLK  144       // persistent grid size (<= 148 SMs -> co-resident)

// ---- gemm4 smem staging (4 arrays x 128x40) ----
#define SOFF_AL 5120
#define SOFF_WH 10240
#define SOFF_WL 15360
#define SST     20480                   // bf16 per stage
#define SMEM_BYTES (2 * SST * 2)        // 81920 B

// ---- persist kernel smem: resident Whi (11 chunks) + 2-stage (Ahi,Alo,Wlo) ----
#define RES_CHUNK   5120                // bf16 per resident chunk (128x40)
#define PST_BASE    56320               // staging base (elems) = 11*5120
#define PST_AL      5120                // within stage
#define PST_WL      10240
#define PSST        15360               // bf16 per stage (3 arrays)
#define PSMEM_BYTES ((PST_BASE + 2 * PSST) * 2)   // 174080 B

typedef __nv_bfloat16 bf16;

// ---------------- weight split pools ------------------------------------------
#define OFF_ATTNIN  0ull
#define OFF_WIH0    3244032ull
#define OFF_WHH0    3735552ull
#define OFF_WIH1    6979584ull
#define OFF_WHH1    10223616ull
#define OFF_FREQ    13467648ull
#define OFF_ATTNOUT 13631488ull
#define OFF_PRE     14712832ull
#define OFF_SPL1    15794176ull
#define WPOOL_TOTAL 17821696ull

__device__ bf16 g_whi[WPOOL_TOTAL];
__device__ bf16 g_wlo[WPOOL_TOTAL];

// ---------------- activation split pool ----------------------------------------
#define OFFA_IN    0ull
#define OFFA_FRQ   4915200ull
#define OFFA_FEAT  7413760ull
#define OFFA_SEQ   23904256ull
#define OFFA_OBAR  56344576ull
#define OFFA_H0    56614912ull
#define OFFA_H1    56885248ull
#define OFFA_HID   57155584ull
#define OFFA_XT    57425920ull
#define APOOL_TOTAL 57466880ull

__device__ bf16 g_ahi[APOOL_TOTAL];
__device__ bf16 g_alo[APOOL_TOTAL];

// ---------------- scratch -------------------------------------------------------
__device__ float g_big[(size_t)BB * TS * GG];
__device__ float g_seq[(size_t)BB * TS * HH];
__device__ float g_in [(size_t)BB * TS * DD];
__device__ float g_frq[(size_t)BB * NF * DD];
__device__ float g_cosm[NF * TS];
__device__ float g_obar[BB * HH];
__device__ float g_mctx[BB * HH];
__device__ float g_h0[BB * HH];
__device__ float g_h1[BB * HH];
__device__ float g_ghp[(size_t)4 * BB * GG];
__device__ float g_gxp[(size_t)4 * BB * GG];
__device__ float g_prep[(size_t)8 * BB * HH];
__device__ float g_splp[(size_t)8 * BB * NJ * 128];
__device__ float g_z1[BB * NJ * 128];
__device__ float g_p6[BB * NJ * 6];

// ---------------- software grid barrier -----------------------------------------
__device__ unsigned g_barcnt = 0;
__device__ unsigned g_barsense = 0;

__device__ __forceinline__ void grid_bar() {
    __syncthreads();
    if (threadIdx.x == 0) {
        unsigned my = *(volatile unsigned*)&g_barsense;
        __threadfence();
        unsigned arrived = atomicAdd(&g_barcnt, 1u);
        if (arrived == NBLK - 1) {
            atomicExch(&g_barcnt, 0u);
            __threadfence();
            atomicExch(&g_barsense, my ^ 1u);
        } else {
            while (*(volatile unsigned*)&g_barsense == my) { }
            __threadfence();
        }
    }
    __syncthreads();
}

// ---------------- cp.async -------------------------------------------------------
__device__ __forceinline__ void cp16(bf16* dst, const bf16* src) {
    unsigned saddr = (unsigned)__cvta_generic_to_shared(dst);
    asm volatile("cp.async.cg.shared.global [%0], [%1], 16;\n" :: "r"(saddr), "l"(src));
}
#define CP_COMMIT() asm volatile("cp.async.commit_group;\n" ::: "memory")
#define CP_WAIT1()  asm volatile("cp.async.wait_group 1;\n" ::: "memory")
#define CP_WAIT0()  asm volatile("cp.async.wait_group 0;\n" ::: "memory")

// gemm4 staging: A 128x32 + W 128x32, hi/lo (4 arrays)
__device__ __forceinline__ void stage_load(
    bf16* sb, const bf16* __restrict__ Ahi, const bf16* __restrict__ Alo,
    const bf16* __restrict__ Whi, const bf16* __restrict__ Wlo,
    int m0, int n0, int k0, int KP, int tid)
{
    #pragma unroll
    for (int it = 0; it < 2; it++) {
        int slot = tid + it * 256;
        int rw = slot >> 2;
        int col = (slot & 3) << 3;
        size_t aoff = (size_t)(m0 + rw) * KP + k0 + col;
        size_t woff = (size_t)(n0 + rw) * KP + k0 + col;
        int so = rw * 40 + col;
        cp16(sb + so,           Ahi + aoff);
        cp16(sb + SOFF_AL + so, Alo + aoff);
        cp16(sb + SOFF_WH + so, Whi + woff);
        cp16(sb + SOFF_WL + so, Wlo + woff);
    }
}

__device__ __forceinline__ void mma_stage(
    const bf16* sb, int wm, int wn,
    wmma::fragment<wmma::accumulator, 16, 16, 16, float> (&acc)[2][4])
{
    #pragma unroll
    for (int kk = 0; kk < 32; kk += 16) {
        wmma::fragment<wmma::matrix_a, 16, 16, 16, bf16, wmma::row_major> faH[2], faL[2];
        #pragma unroll
        for (int i = 0; i < 2; i++) {
            wmma::load_matrix_sync(faH[i], sb + (wm * 32 + i * 16) * 40 + kk, 40);
            wmma::load_matrix_sync(faL[i], sb + SOFF_AL + (wm * 32 + i * 16) * 40 + kk, 40);
        }
        #pragma unroll
        for (int j = 0; j < 4; j++) {
            wmma::fragment<wmma::matrix_b, 16, 16, 16, bf16, wmma::col_major> fbH, fbL;
            wmma::load_matrix_sync(fbH, sb + SOFF_WH + (wn * 64 + j * 16) * 40 + kk, 40);
            wmma::load_matrix_sync(fbL, sb + SOFF_WL + (wn * 64 + j * 16) * 40 + kk, 40);
            #pragma unroll
            for (int i = 0; i < 2; i++) {
                wmma::mma_sync(acc[i][j], faH[i], fbH, acc[i][j]);
                wmma::mma_sync(acc[i][j], faH[i], fbL, acc[i][j]);
                wmma::mma_sync(acc[i][j], faL[i], fbH, acc[i][j]);
            }
        }
    }
}

// ---------------- small utility kernels -----------------------------------------

__global__ void copy_inseq_kernel(const float* __restrict__ poses, float* __restrict__ dst) {
    int idx = blockIdx.x * 256 + threadIdx.x;
    if (idx >= BB * TS * DD) return;
    int d = idx % DD;
    int t = (idx / DD) % TS;
    int b = idx / (TS * DD);
    dst[idx] = poses[((size_t)b * (TS + PREDN) + t) * DD + d];
}

__global__ void build_cos_kernel(float* __restrict__ cosm) {
    int idx = blockIdx.x * 256 + threadIdx.x;
    if (idx >= NF * TS) return;
    int f = idx / TS, t = idx % TS;
    cosm[idx] = (float)cos(2.0 * 3.14159265358979323846 * (double)(f * t) / (double)TS);
}

__global__ void freq_kernel(const float* __restrict__ inseq, const float* __restrict__ cosm,
                            float* __restrict__ freq) {
    int b = blockIdx.x, f = blockIdx.y, d = threadIdx.x;
    if (d >= DD) return;
    const float* xp = inseq + (size_t)b * TS * DD + d;
    const float* cp = cosm + f * TS;
    float s = 0.f;
    #pragma unroll 4
    for (int t = 0; t < TS; t++) s += cp[t] * xp[(size_t)t * DD];
    freq[((size_t)b * NF + f) * DD + d] = s;
}

// ---------------- splitters -------------------------------------------------------
__global__ void split_w_kernel(const float* __restrict__ W, const float* __restrict__ bias,
                               bf16* __restrict__ hi, bf16* __restrict__ lo,
                               int N, int K, int KP) {
    size_t idx = (size_t)blockIdx.x * 256 + threadIdx.x;
    if (idx >= (size_t)N * KP) return;
    int k = (int)(idx % KP);
    int n = (int)(idx / KP);
    float v = 0.f;
    if (k < K) v = W[(size_t)n * K + k];
    else if (k == K) v = bias[n];
    bf16 h = __float2bfloat16(v);
    hi[idx] = h;
    lo[idx] = __float2bfloat16(v - __bfloat162float(h));
}

__global__ void split_a_kernel(const float* __restrict__ A,
                               bf16* __restrict__ hi, bf16* __restrict__ lo,
                               int M, int K, int KP) {
    size_t idx = (size_t)blockIdx.x * 256 + threadIdx.x;
    if (idx >= (size_t)M * KP) return;
    int k = (int)(idx % KP);
    int m = (int)(idx / KP);
    float v = 0.f;
    if (k < K) v = A[(size_t)m * K + k];
    else if (k == K) v = 1.0f;
    bf16 h = __float2bfloat16(v);
    hi[idx] = h;
    lo[idx] = __float2bfloat16(v - __bfloat162float(h));
}

// full init (data cols zero + ones col) -- for h buffers read before first write
__global__ void zero_split_kernel(bf16* __restrict__ hi, bf16* __restrict__ lo,
                                  int M, int K, int KP) {
    size_t idx = (size_t)blockIdx.x * 256 + threadIdx.x;
    if (idx >= (size_t)M * KP) return;
    int k = (int)(idx % KP);
    float v = (k == K) ? 1.0f : 0.0f;
    hi[idx] = __float2bfloat16(v);
    lo[idx] = __float2bfloat16(0.0f);
}

// pad-only init (cols K..KP-1) -- data cols are fully written by producers
__global__ void pad_init_kernel(bf16* __restrict__ hi, bf16* __restrict__ lo,
                                int M, int K, int KP) {
    int PAD = KP - K;
    size_t idx = (size_t)blockIdx.x * 256 + threadIdx.x;
    if (idx >= (size_t)M * PAD) return;
    int p = (int)(idx % PAD);
    int m = (int)(idx / PAD);
    size_t o = (size_t)m * KP + K + p;
    float v = (p == 0) ? 1.0f : 0.0f;   // col K = ones (bias), rest zero
    hi[o] = __float2bfloat16(v);
    lo[o] = __float2bfloat16(0.0f);
}

// ---------------- gemm4 (batch / decode) -------------------------------------------
__global__ __launch_bounds__(256, 2) void gemm4_kernel(
    const bf16* __restrict__ Ahi, const bf16* __restrict__ Alo,
    const bf16* __restrict__ Whi, const bf16* __restrict__ Wlo,
    float* __restrict__ C, int M, int N, int KP)
{
    extern __shared__ __align__(16) bf16 sm4[];
    int tid = threadIdx.x;
    int warp = tid >> 5;
    int wm = warp >> 1, wn = warp & 1;
    int m0 = blockIdx.y * 128, n0 = blockIdx.x * 128;

    wmma::fragment<wmma::accumulator, 16, 16, 16, float> acc[2][4];
    #pragma unroll
    for (int i = 0; i < 2; i++)
        #pragma unroll
        for (int j = 0; j < 4; j++)
            wmma::fill_fragment(acc[i][j], 0.0f);

    int CH  = KP >> 5;
    int cpz = (CH + gridDim.z - 1) / gridDim.z;
    int c0  = blockIdx.z * cpz;
    int c1  = c0 + cpz; if (c1 > CH) c1 = CH;
    int nch = c1 - c0;

    if (nch > 0) {
        stage_load(sm4, Ahi, Alo, Whi, Wlo, m0, n0, c0 << 5, KP, tid);
        CP_COMMIT();
    }
    for (int i = 0; i < nch; i++) {
        bf16* sb = sm4 + (i & 1) * SST;
        if (i + 1 < nch) {
            stage_load(sm4 + ((i + 1) & 1) * SST, Ahi, Alo, Whi, Wlo,
                       m0, n0, (c0 + i + 1) << 5, KP, tid);
            CP_COMMIT();
            CP_WAIT1();
        } else {
            CP_WAIT0();
        }
        __syncthreads();
        mma_stage(sb, wm, wn, acc);
        __syncthreads();
    }

    float* Cz = C + (size_t)blockIdx.z * M * N;
    #pragma unroll
    for (int i = 0; i < 2; i++)
        #pragma unroll
        for (int j = 0; j < 4; j++)
            wmma::store_matrix_sync(
                Cz + (size_t)(m0 + wm * 32 + i * 16) * N + (n0 + wn * 64 + j * 16),
                acc[i][j], N, wmma::mem_row_major);
}

// ---------------- persistent GRU recurrence (Whi-resident in smem) ----------------
// 144 CTAs: tile = blockIdx%48 (2m x 24n of 128x128), slice = blockIdx/48 (11 chunks).
// Whi slice (11 chunks x 128x32) preloaded once; per chunk stream Ahi/Alo/Wlo.
__global__ __launch_bounds__(256, 1) void gru_persist_kernel(
    const float* __restrict__ gi,          // (B, TS, GG), bih fused
    const bf16* __restrict__ Whi,          // (GG, KP1024), bhh in col HH
    const bf16* __restrict__ Wlo,
    float* __restrict__ h,                 // (B, HH) fp32, pre-zeroed
    bf16* __restrict__ hhi,                // (B, KP1024), pre-inited
    bf16* __restrict__ hlo,
    float* __restrict__ ghp,               // (3, B, GG) partials
    bf16* __restrict__ seqhi,              // (B, TS, KP1024) or null
    bf16* __restrict__ seqlo,
    int nsteps)
{
    extern __shared__ __align__(16) bf16 sm4[];
    bf16* wres = sm4;                       // resident Whi: chunk c at c*RES_CHUNK
    bf16* stg  = sm4 + PST_BASE;            // 2 stages of (Ahi, Alo, Wlo)
    int tid = threadIdx.x;
    int warp = tid >> 5;
    int wm = warp >> 1, wn = warp & 1;
    int tile  = blockIdx.x % 48;
    int slice = blockIdx.x / 48;            // 0..2
    int m0 = (tile / 24) * 128;
    int n0 = (tile % 24) * 128;
    const int c0 = slice * 11;

    // ---- one-time Whi preload into resident smem ----
    for (int c = 0; c < 11; c++) {
        int k0 = (c0 + c) << 5;
        #pragma unroll
        for (int it = 0; it < 2; it++) {
            int slot = tid + it * 256;
            int rw = slot >> 2;
            int col = (slot & 3) << 3;
            cp16(wres + c * RES_CHUNK + rw * 40 + col,
                 Whi + (size_t)(n0 + rw) * KP1024 + k0 + col);
        }
    }
    CP_COMMIT();
    CP_WAIT0();
    __syncthreads();

    for (int t = 0; t < nsteps; t++) {
        // ---- phase 1: partial gh = h @ Whh^T over this k-slice ----
        wmma::fragment<wmma::accumulator, 16, 16, 16, float> acc[2][4];
        #pragma unroll
        for (int i = 0; i < 2; i++)
            #pragma unroll
            for (int j = 0; j < 4; j++)
                wmma::fill_fragment(acc[i][j], 0.0f);

        // prefetch chunk 0 (Ahi, Alo, Wlo)
        {
            int k0 = c0 << 5;
            #pragma unroll
            for (int it = 0; it < 2; it++) {
                int slot = tid + it * 256;
                int rw = slot >> 2;
                int col = (slot & 3) << 3;
                size_t aoff = (size_t)(m0 + rw) * KP1024 + k0 + col;
                size_t woff = (size_t)(n0 + rw) * KP1024 + k0 + col;
                int so = rw * 40 + col;
                cp16(stg + so,          hhi + aoff);
                cp16(stg + PST_AL + so, hlo + aoff);
                cp16(stg + PST_WL + so, Wlo + woff);
            }
            CP_COMMIT();
        }

        #pragma unroll 1
        for (int i = 0; i < 11; i++) {
            bf16* sb = stg + (i & 1) * PSST;
            if (i + 1 < 11) {
                bf16* nb = stg + ((i + 1) & 1) * PSST;
                int k0 = (c0 + i + 1) << 5;
                #pragma unroll
                for (int it = 0; it < 2; it++) {
                    int slot = tid + it * 256;
                    int rw = slot >> 2;
                    int col = (slot & 3) << 3;
                    size_t aoff = (size_t)(m0 + rw) * KP1024 + k0 + col;
                    size_t woff = (size_t)(n0 + rw) * KP1024 + k0 + col;
                    int so = rw * 40 + col;
                    cp16(nb + so,          hhi + aoff);
                    cp16(nb + PST_AL + so, hlo + aoff);
                    cp16(nb + PST_WL + so, Wlo + woff);
                }
                CP_COMMIT();
                CP_WAIT1();
            } else {
                CP_WAIT0();
            }
            __syncthreads();
            const bf16* wre = wres + i * RES_CHUNK;
            #pragma unroll
            for (int kk = 0; kk < 32; kk += 16) {
                wmma::fragment<wmma::matrix_a, 16, 16, 16, bf16, wmma::row_major> faH[2], faL[2];
                #pragma unroll
                for (int ii = 0; ii < 2; ii++) {
                    wmma::load_matrix_sync(faH[ii], sb + (wm * 32 + ii * 16) * 40 + kk, 40);
                    wmma::load_matrix_sync(faL[ii], sb + PST_AL + (wm * 32 + ii * 16) * 40 + kk, 40);
                }
                #pragma unroll
                for (int j = 0; j < 4; j++) {
                    wmma::fragment<wmma::matrix_b, 16, 16, 16, bf16, wmma::col_major> fbH, fbL;
                    wmma::load_matrix_sync(fbH, wre + (wn * 64 + j * 16) * 40 + kk, 40);
                    wmma::load_matrix_sync(fbL, sb + PST_WL + (wn * 64 + j * 16) * 40 + kk, 40);
                    #pragma unroll
                    for (int ii = 0; ii < 2; ii++) {
                        wmma::mma_sync(acc[ii][j], faH[ii], fbH, acc[ii][j]);
                        wmma::mma_sync(acc[ii][j], faH[ii], fbL, acc[ii][j]);
                        wmma::mma_sync(acc[ii][j], faL[ii], fbH, acc[ii][j]);
                    }
                }
            }
            __syncthreads();
        }

        float* Cz = ghp + (size_t)slice * (BB * GG);
        #pragma unroll
        for (int i = 0; i < 2; i++)
            #pragma unroll
            for (int j = 0; j < 4; j++)
                wmma::store_matrix_sync(
                    Cz + (size_t)(m0 + wm * 32 + i * 16) * GG + (n0 + wn * 64 + j * 16),
                    acc[i][j], GG, wmma::mem_row_major);

        __threadfence();
        grid_bar();

        // ---- phase 2: gate math ----
        for (int idx = blockIdx.x * 256 + tid; idx < BB * HH; idx += NBLK * 256) {
            int b = idx >> 10, j = idx & 1023;
            const float* gib = gi + ((size_t)b * TS + t) * GG;
            float ir = gib[j], iz = gib[HH + j], inn = gib[2 * HH + j];
            float hr = 0.f, hz = 0.f, hn = 0.f;
            #pragma unroll
            for (int s = 0; s < 3; s++) {
                const float* g = ghp + (size_t)s * (BB * GG) + (size_t)b * GG;
                hr += __ldcg(&g[j]);
                hz += __ldcg(&g[HH + j]);
                hn += __ldcg(&g[2 * HH + j]);
            }
            float r = 1.f / (1.f + expf(-(ir + hr)));
            float z = 1.f / (1.f + expf(-(iz + hz)));
            float n = tanhf(inn + r * hn);
            float hp = __ldcg(&h[idx]);
            float hnew = (1.f - z) * n + z * hp;
            h[idx] = hnew;
            bf16 hb = __float2bfloat16(hnew);
            bf16 lb = __float2bfloat16(hnew - __bfloat162float(hb));
            size_t ho = (size_t)b * KP1024 + j;
            hhi[ho] = hb;
            hlo[ho] = lb;
            if (seqhi) {
                size_t so = ((size_t)b * TS + t) * KP1024 + j;
                seqhi[so] = hb;
                seqlo[so] = lb;
            }
        }
        __threadfence();
        grid_bar();
    }
}

// ---------------- attention --------------------------------------------------------
__global__ __launch_bounds__(256) void attention_kernel(const float* __restrict__ qkv,
                                                        float* __restrict__ o) {
    extern __shared__ float sm[];
    float* kv = sm;
    float* sc = sm + NF * DHD;
    int b = blockIdx.x >> 2;
    int h = blockIdx.x & 3;
    int tid = threadIdx.x;
    int lane = tid & 31, w = tid >> 5;
    const float* base = qkv + (size_t)b * NF * GG + h * DHD;

    for (int idx = tid; idx < NF * DHD; idx += 256) {
        int t = idx >> 8, d = idx & 255;
        kv[idx] = base[(size_t)t * GG + HH + d];
    }
    __syncthreads();
    for (int i = w; i < NF; i += 8) {
        float q[8];
        const float* qp = base + (size_t)i * GG;
        #pragma unroll
        for (int c = 0; c < 8; c++) q[c] = qp[lane + 32 * c];
        for (int j = 0; j < NF; j++) {
            const float* kp = kv + j * DHD;
            float s = 0.f;
            #pragma unroll
            for (int c = 0; c < 8; c++) s += q[c] * kp[lane + 32 * c];
            #pragma unroll
            for (int off = 16; off; off >>= 1) s += __shfl_xor_sync(0xffffffffu, s, off);
            if (lane == 0) sc[i * 64 + j] = s * 0.0625f;
        }
    }
    __syncthreads();
    for (int i = w; i < NF; i += 8) {
        float v0 = (lane < NF) ? sc[i * 64 + lane] : -1e30f;
        float v1 = (lane + 32 < NF) ? sc[i * 64 + lane + 32] : -1e30f;
        float m = fmaxf(v0, v1);
        #pragma unroll
        for (int off = 16; off; off >>= 1) m = fmaxf(m, __shfl_xor_sync(0xffffffffu, m, off));
        float e0 = (lane < NF) ? expf(v0 - m) : 0.f;
        float e1 = (lane + 32 < NF) ? expf(v1 - m) : 0.f;
        float ss = e0 + e1;
        #pragma unroll
        for (int off = 16; off; off >>= 1) ss += __shfl_xor_sync(0xffffffffu, ss, off);
        float inv = 1.f / ss;
        if (lane < NF) sc[i * 64 + lane] = e0 * inv;
        if (lane + 32 < NF) sc[i * 64 + lane + 32] = e1 * inv;
    }
    __syncthreads();
    for (int idx = tid; idx < NF * DHD; idx += 256) {
        int t = idx >> 8, d = idx & 255;
        kv[idx] = base[(size_t)t * GG + 2 * HH + d];
    }
    __syncthreads();
    float acc[NF];
    #pragma unroll
    for (int i = 0; i < NF; i++) acc[i] = 0.f;
    int d = tid;
    for (int j = 0; j < NF; j++) {
        float vv = kv[j * DHD + d];
        #pragma unroll
        for (int i = 0; i < NF; i++) acc[i] += sc[i * 64 + j] * vv;
    }
    float* ob = o + (size_t)b * NF * HH + h * DHD + d;
    #pragma unroll
    for (int i = 0; i < NF; i++) ob[(size_t)i * HH] = acc[i];
}

__global__ void mean61_kernel(const float* __restrict__ o, float* __restrict__ obar) {
    int idx = blockIdx.x * 256 + threadIdx.x;
    if (idx >= BB * HH) return;
    int b = idx >> 10, c = idx & 1023;
    const float* p = o + (size_t)b * NF * HH + c;
    float s = 0.f;
    for (int t = 0; t < NF; t++) s += p[(size_t)t * HH];
    obar[idx] = s * (1.f / (float)NF);
}

// ---------------- decode gate -------------------------------------------------------
__global__ void gru_gate2(const float* __restrict__ gxp, int gx_sk,
                          const float* __restrict__ ghp, int gh_sk,
                          float* __restrict__ h,
                          bf16* __restrict__ hhi, bf16* __restrict__ hlo) {
    int idx = blockIdx.x * 256 + threadIdx.x;
    if (idx >= BB * HH) return;
    int b = idx >> 10, j = idx & 1023;
    float ir = 0.f, iz = 0.f, in = 0.f;
    for (int s = 0; s < gx_sk; s++) {
        const float* g = gxp + (size_t)s * (BB * GG) + (size_t)b * GG;
        ir += g[j]; iz += g[HH + j]; in += g[2 * HH + j];
    }
    float hr = 0.f, hz = 0.f, hn = 0.f;
    for (int s = 0; s < gh_sk; s++) {
        const float* g = ghp + (size_t)s * (BB * GG) + (size_t)b * GG;
        hr += g[j]; hz += g[HH + j]; hn += g[2 * HH + j];
    }
    float r = 1.f / (1.f + expf(-(ir + hr)));
    float z = 1.f / (1.f + expf(-(iz + hz)));
    float n = tanhf(in + r * hn);
    float hp = h[idx];
    float hnew = (1.f - z) * n + z * hp;
    h[idx] = hnew;
    bf16 hb = __float2bfloat16(hnew);
    size_t ho = (size_t)b * KP1024 + j;
    hhi[ho] = hb;
    hlo[ho] = __float2bfloat16(hnew - __bfloat162float(hb));
}

// ---------------- split-K reductions ------------------------------------------------
__global__ void reduce_act_kernel(const float* __restrict__ part, int sk, int mn,
                                  float* __restrict__ out) {
    int idx = blockIdx.x * 256 + threadIdx.x;
    if (idx >= mn) return;
    float s = 0.f;
    for (int i = 0; i < sk; i++) s += part[(size_t)i * mn + idx];
    out[idx] = fmaxf(s, 0.f);
}

__global__ void reduce_split_kernel(const float* __restrict__ part, int sk,
                                    const float* __restrict__ addend,
                                    bf16* __restrict__ hi, bf16* __restrict__ lo) {
    int idx = blockIdx.x * 256 + threadIdx.x;
    if (idx >= BB * HH) return;
    int b = idx >> 10, j = idx & 1023;
    float s = 0.f;
    for (int i = 0; i < sk; i++) s += part[(size_t)i * (BB * HH) + idx];
    s = fmaxf(s, 0.f) + addend[idx];
    bf16 hb = __float2bfloat16(s);
    size_t o = (size_t)b * KP1024 + j;
    hi[o] = hb;
    lo[o] = __float2bfloat16(s - __bfloat162float(hb));
}

// ---------------- decode init ---------------------------------------------------------
__global__ void init_decode(const float* __restrict__ inseq,
                            bf16* __restrict__ xthi, bf16* __restrict__ xtlo,
                            float* __restrict__ p6) {
    int idx = blockIdx.x * 256 + threadIdx.x;
    if (idx >= BB * KP135) return;
    int b = idx / KP135, d = idx % KP135;
    const float* last = inseq + ((size_t)b * TS + (TS - 1)) * DD;
    float v = 0.f;
    if (d < DD) v = last[d];
    else if (d == DD) v = 1.0f;
    bf16 hb = __float2bfloat16(v);
    xthi[idx] = hb;
    xtlo[idx] = __float2bfloat16(v - __bfloat162float(hb));
    if (d < NJ * 6) {
        int j = d / 6, o = d % 6;
        int src = (o < 3) ? (j * 9 + o * 3) : (j * 9 + (o - 3) * 3 + 1);
        p6[(size_t)b * 90 + d] = last[src];
    }
}

// ---------------- spl head layer2 + rot6d -------------------------------------------
__global__ __launch_bounds__(192) void spl2_rot(const float* __restrict__ z1,
                                                const float* __restrict__ w2,
                                                const float* __restrict__ b2,
                                                float* __restrict__ p6,
                                                bf16* __restrict__ xthi,
                                                bf16* __restrict__ xtlo,
                                                float* __restrict__ out, int step) {
    int bj = blockIdx.x;
    int b = bj / NJ, j = bj % NJ;
    int w = threadIdx.x >> 5, lane = threadIdx.x & 31;
    __shared__ float v6[6];
    const float* zz = z1 + (size_t)b * (NJ * 128) + j * 128;
    const float* ww = w2 + ((size_t)j * 6 + w) * 128;
    float s = 0.f;
    #pragma unroll
    for (int c = 0; c < 4; c++) s += zz[lane + 32 * c] * ww[lane + 32 * c];
    #pragma unroll
    for (int off = 16; off; off >>= 1) s += __shfl_xor_sync(0xffffffffu, s, off);
    if (lane == 0)
        v6[w] = p6[(size_t)b * 90 + j * 6 + w] + s + b2[j * 6 + w];
    __syncthreads();
    if (threadIdx.x < 6) {
        float v = v6[threadIdx.x];
        p6[(size_t)b * 90 + j * 6 + threadIdx.x] = v;
        out[((size_t)b * PREDN + step) * 90 + j * 6 + threadIdx.x] = v;
    }
    if (threadIdx.x == 0) {
        float a1x = v6[0], a2x = v6[1], a1y = v6[2], a2y = v6[3], a1z = v6[4], a2z = v6[5];
        float n1 = fmaxf(sqrtf(a1x*a1x + a1y*a1y + a1z*a1z), 1e-12f);
        float b1x = a1x / n1, b1y = a1y / n1, b1z = a1z / n1;
        float dot = b1x*a2x + b1y*a2y + b1z*a2z;
        float ox = a2x - dot*b1x, oy = a2y - dot*b1y, oz = a2z - dot*b1z;
        float n2 = fmaxf(sqrtf(ox*ox + oy*oy + oz*oz), 1e-12f);
        float b2x = ox / n2, b2y = oy / n2, b2z = oz / n2;
        float b3x = b1y*b2z - b1z*b2y;
        float b3y = b1z*b2x - b1x*b2z;
        float b3z = b1x*b2y - b1y*b2x;
        float rm[9] = { b1x, b2x, b3x, b1y, b2y, b3y, b1z, b2z, b3z };
        size_t base = (size_t)b * KP135 + j * 9;
        #pragma unroll
        for (int c = 0; c < 9; c++) {
            bf16 hb = __float2bfloat16(rm[c]);
            xthi[base + c] = hb;
            xtlo[base + c] = __float2bfloat16(rm[c] - __bfloat162float(hb));
        }
    }
}

// ---------------- host orchestration --------------------------------------------------

static inline void gemm4(const bf16* ahi, const bf16* alo,
                         const bf16* whi, const bf16* wlo,
                         float* C, int M, int N, int KP, int sk) {
    dim3 g(N / 128, M / 128, sk);
    gemm4_kernel<<<g, 256, SMEM_BYTES>>>(ahi, alo, whi, wlo, C, M, N, KP);
}

static inline void splitw(const float* W, const float* bias,
                          bf16* hi, bf16* lo, int N, int K, int KP) {
    size_t n = (size_t)N * KP;
    split_w_kernel<<<(int)((n + 255) / 256), 256>>>(W, bias, hi, lo, N, K, KP);
}

static inline void splita(const float* A, bf16* hi, bf16* lo, int M, int K, int KP) {
    size_t n = (size_t)M * KP;
    split_a_kernel<<<(int)((n + 255) / 256), 256>>>(A, hi, lo, M, K, KP);
}

static inline void zerosplit(bf16* hi, bf16* lo, int M, int K, int KP) {
    size_t n = (size_t)M * KP;
    zero_split_kernel<<<(int)((n + 255) / 256), 256>>>(hi, lo, M, K, KP);
}

static inline void padinit(bf16* hi, bf16* lo, int M, int K, int KP) {
    size_t n = (size_t)M * (KP - K);
    pad_init_kernel<<<(int)((n + 255) / 256), 256>>>(hi, lo, M, K, KP);
}

extern "C" void kernel_launch(void* const* d_in, const int* in_sizes, int n_in,
                              void* d_out, int out_size) {
    const float* poses      = (const float*)d_in[0];
    const float* freq_w     = (const float*)d_in[1];
    const float* freq_b     = (const float*)d_in[2];
    const float* attn_in_w  = (const float*)d_in[3];
    const float* attn_in_b  = (const float*)d_in[4];
    const float* attn_out_w = (const float*)d_in[5];
    const float* attn_out_b = (const float*)d_in[6];
    const float* gru_wih0   = (const float*)d_in[7];
    const float* gru_whh0   = (const float*)d_in[8];
    const float* gru_bih0   = (const float*)d_in[9];
    const float* gru_bhh0   = (const float*)d_in[10];
    const float* gru_wih1   = (const float*)d_in[11];
    const float* gru_whh1   = (const float*)d_in[12];
    const float* gru_bih1   = (const float*)d_in[13];
    const float* gru_bhh1   = (const float*)d_in[14];
    const float* pre_w      = (const float*)d_in[15];
    const float* pre_b      = (const float*)d_in[16];
    const float* spl_w1     = (const float*)d_in[17];
    const float* spl_b1     = (const float*)d_in[18];
    const float* spl_w2     = (const float*)d_in[19];
    const float* spl_b2     = (const float*)d_in[20];
    float* out = (float*)d_out;

    float *pBig, *pSeq, *pIn, *pFrq, *pCos, *pObar, *pMctx, *pH0, *pH1,
          *pGhp, *pGxp, *pPrep, *pSplp, *pZ1, *pP6;
    bf16 *pWhi, *pWlo, *pAhi, *pAlo;
    cudaGetSymbolAddress((void**)&pBig, g_big);
    cudaGetSymbolAddress((void**)&pSeq, g_seq);
    cudaGetSymbolAddress((void**)&pIn,  g_in);
    cudaGetSymbolAddress((void**)&pFrq, g_frq);
    cudaGetSymbolAddress((void**)&pCos, g_cosm);
    cudaGetSymbolAddress((void**)&pObar, g_obar);
    cudaGetSymbolAddress((void**)&pMctx, g_mctx);
    cudaGetSymbolAddress((void**)&pH0, g_h0);
    cudaGetSymbolAddress((void**)&pH1, g_h1);
    cudaGetSymbolAddress((void**)&pGhp, g_ghp);
    cudaGetSymbolAddress((void**)&pGxp, g_gxp);
    cudaGetSymbolAddress((void**)&pPrep, g_prep);
    cudaGetSymbolAddress((void**)&pSplp, g_splp);
    cudaGetSymbolAddress((void**)&pZ1, g_z1);
    cudaGetSymbolAddress((void**)&pP6, g_p6);
    cudaGetSymbolAddress((void**)&pWhi, g_whi);
    cudaGetSymbolAddress((void**)&pWlo, g_wlo);
    cudaGetSymbolAddress((void**)&pAhi, g_ahi);
    cudaGetSymbolAddress((void**)&pAlo, g_alo);

    cudaFuncSetAttribute(gemm4_kernel, cudaFuncAttributeMaxDynamicSharedMemorySize, SMEM_BYTES);
    cudaFuncSetAttribute(gru_persist_kernel, cudaFuncAttributeMaxDynamicSharedMemorySize, PSMEM_BYTES);

    float* qkv   = pBig;
    float* attno = pBig + (size_t)BB * NF * GG;
    float* gi    = pBig;
    float* feat  = pSeq;

    const int BF = BB * NF;
    const int BT = BB * TS;

    // ---- first 4 launches: diag gemm4 is MY #4 (observed ncu-profiled slot) ----
    copy_inseq_kernel<<<(BB*TS*DD + 255) / 256, 256>>>(poses, pIn);              // 1
    build_cos_kernel<<<(NF*TS + 255) / 256, 256>>>(pCos);                        // 2
    splitw(attn_in_w, attn_in_b, pWhi + OFF_ATTNIN, pWlo + OFF_ATTNIN,
           GG, HH, KP1024);                                                      // 3
    gemm4(pWhi + OFF_ATTNIN, pWlo + OFF_ATTNIN,
          pWhi + OFF_ATTNIN, pWlo + OFF_ATTNIN, pBig, 1536, GG, KP1024, 1);      // 4 DIAG

    // ---- remaining weight splits ----
    splitw(gru_wih0,  gru_bih0,  pWhi + OFF_WIH0,    pWlo + OFF_WIH0,    GG, DD, KP135);
    splitw(gru_whh0,  gru_bhh0,  pWhi + OFF_WHH0,    pWlo + OFF_WHH0,    GG, HH, KP1024);
    splitw(gru_wih1,  gru_bih1,  pWhi + OFF_WIH1,    pWlo + OFF_WIH1,    GG, HH, KP1024);
    splitw(gru_whh1,  gru_bhh1,  pWhi + OFF_WHH1,    pWlo + OFF_WHH1,    GG, HH, KP1024);
    splitw(freq_w,    freq_b,    pWhi + OFF_FREQ,    pWlo + OFF_FREQ,    HH, DD, KP135);
    splitw(attn_out_w,attn_out_b,pWhi + OFF_ATTNOUT, pWlo + OFF_ATTNOUT, HH, HH, KP1024);
    splitw(pre_w,     pre_b,     pWhi + OFF_PRE,     pWlo + OFF_PRE,     HH, HH, KP1024);
    splitw(spl_w1,    spl_b1,    pWhi + OFF_SPL1,    pWlo + OFF_SPL1,    NJ*128, HH, KP1024);

    // ---- activation split buffer init ----
    padinit(pAhi + OFFA_SEQ, pAlo + OFFA_SEQ, BT, HH, KP1024);   // data cols written by GRU0
    zerosplit(pAhi + OFFA_H0,  pAlo + OFFA_H0,  BB, HH, KP1024); // read before first write
    zerosplit(pAhi + OFFA_H1,  pAlo + OFFA_H1,  BB, HH, KP1024);
    padinit(pAhi + OFFA_HID, pAlo + OFFA_HID, BB, HH, KP1024);   // data cols written by reduce

    // ---- frequency attention branch ----
    freq_kernel<<<dim3(BB, NF), 160>>>(pIn, pCos, pFrq);
    splita(pFrq, pAhi + OFFA_FRQ, pAlo + OFFA_FRQ, BF, DD, KP135);
    gemm4(pAhi + OFFA_FRQ, pAlo + OFFA_FRQ, pWhi + OFF_FREQ, pWlo + OFF_FREQ,
          feat, BF, HH, KP135, 1);
    splita(feat, pAhi + OFFA_FEAT, pAlo + OFFA_FEAT, BF, HH, KP1024);
    gemm4(pAhi + OFFA_FEAT, pAlo + OFFA_FEAT, pWhi + OFF_ATTNIN, pWlo + OFF_ATTNIN,
          qkv, BF, GG, KP1024, 1);

    int smem_attn = (NF * DHD + NF * 64) * (int)sizeof(float);
    cudaFuncSetAttribute(attention_kernel, cudaFuncAttributeMaxDynamicSharedMemorySize, smem_attn);
    attention_kernel<<<BB * NHEAD, 256, smem_attn>>>(qkv, attno);
    mean61_kernel<<<(BB*HH + 255) / 256, 256>>>(attno, pObar);
    splita(pObar, pAhi + OFFA_OBAR, pAlo + OFFA_OBAR, BB, HH, KP1024);
    gemm4(pAhi + OFFA_OBAR, pAlo + OFFA_OBAR, pWhi + OFF_ATTNOUT, pWlo + OFF_ATTNOUT,
          pMctx, BB, HH, KP1024, 1);

    // ---- GRU layer 0 (persistent recurrence, Whi-resident) ----
    splita(pIn, pAhi + OFFA_IN, pAlo + OFFA_IN, BT, DD, KP135);
    gemm4(pAhi + OFFA_IN, pAlo + OFFA_IN, pWhi + OFF_WIH0, pWlo + OFF_WIH0,
          gi, BT, GG, KP135, 1);
    cudaMemsetAsync(pH0, 0, (size_t)BB * HH * sizeof(float));
    gru_persist_kernel<<<NBLK, 256, PSMEM_BYTES>>>(gi, pWhi + OFF_WHH0, pWlo + OFF_WHH0,
                                      pH0, pAhi + OFFA_H0, pAlo + OFFA_H0, pGhp,
                                      pAhi + OFFA_SEQ, pAlo + OFFA_SEQ, TS);

    // ---- GRU layer 1 ----
    gemm4(pAhi + OFFA_SEQ, pAlo + OFFA_SEQ, pWhi + OFF_WIH1, pWlo + OFF_WIH1,
          gi, BT, GG, KP1024, 1);
    cudaMemsetAsync(pH1, 0, (size_t)BB * HH * sizeof(float));
    gru_persist_kernel<<<NBLK, 256, PSMEM_BYTES>>>(gi, pWhi + OFF_WHH1, pWlo + OFF_WHH1,
                                      pH1, pAhi + OFFA_H1, pAlo + OFFA_H1, pGhp,
                                      nullptr, nullptr, TS);

    // ---- autoregressive decode (R7 configuration) ----
    init_decode<<<(BB*KP135 + 255) / 256, 256>>>(pIn, pAhi + OFFA_XT, pAlo + OFFA_XT, pP6);
    for (int s = 0; s < PREDN; s++) {
        gemm4(pAhi + OFFA_XT, pAlo + OFFA_XT, pWhi + OFF_WIH0, pWlo + OFF_WIH0,
              pGxp, BB, GG, KP135, 2);
        gemm4(pAhi + OFFA_H0, pAlo + OFFA_H0, pWhi + OFF_WHH0, pWlo + OFF_WHH0,
              pGhp, BB, GG, KP1024, 4);
        gru_gate2<<<(BB*HH)/256, 256>>>(pGxp, 2, pGhp, 4, pH0,
                                        pAhi + OFFA_H0, pAlo + OFFA_H0);

        gemm4(pAhi + OFFA_H0, pAlo + OFFA_H0, pWhi + OFF_WIH1, pWlo + OFF_WIH1,
              pGxp, BB, GG, KP1024, 4);
        gemm4(pAhi + OFFA_H1, pAlo + OFFA_H1, pWhi + OFF_WHH1, pWlo + OFF_WHH1,
              pGhp, BB, GG, KP1024, 4);
        gru_gate2<<<(BB*HH)/256, 256>>>(pGxp, 4, pGhp, 4, pH1,
                                        pAhi + OFFA_H1, pAlo + OFFA_H1);

        gemm4(pAhi + OFFA_H1, pAlo + OFFA_H1, pWhi + OFF_PRE, pWlo + OFF_PRE,
              pPrep, BB, HH, KP1024, 8);
        reduce_split_kernel<<<(BB*HH + 255)/256, 256>>>(pPrep, 8, pMctx,
                                                        pAhi + OFFA_HID, pAlo + OFFA_HID);

        gemm4(pAhi + OFFA_HID, pAlo + OFFA_HID, pWhi + OFF_SPL1, pWlo + OFF_SPL1,
              pSplp, BB, NJ*128, KP1024, 8);
        reduce_act_kernel<<<(BB*NJ*128 + 255)/256, 256>>>(pSplp, 8, BB*NJ*128, pZ1);

        spl2_rot<<<BB * NJ, 192>>>(pZ1, spl_w2, spl_b2, pP6,
                                   pAhi + OFFA_XT, pAlo + OFFA_XT, out, s);
    }
}

// round 11
// speedup vs baseline: 1.1148x; 1.0299x over previous
#include <cuda_runtime.h>
#include <cuda_bf16.h>
#include <mma.h>
#include <math.h>

using namespace nvcuda;

#define BB    256
#define TS    120
#define PREDN 24
#define NJ    15
#define HH    1024
#define DD    135
#define NF    61
#define GG    3072
#define NHEAD 4
#define DHD   256

#define KP1024 1056
#define KP135  160

#define NBLK  144       // persistent grid size (<= 148 SMs -> co-resident)

// ---- gemm smem staging (4 arrays x 128x40) ----
#define SOFF_AL 5120
#define SOFF_WH 10240
#define SOFF_WL 15360
#define SST     20480                   // bf16 per stage
#define SMEM_BYTES (2 * SST * 2)        // 81920 B

typedef __nv_bfloat16 bf16;

// ---------------- weight split pools ------------------------------------------
#define OFF_ATTNIN  0ull
#define OFF_WIH0    3244032ull
#define OFF_WHH0    3735552ull
#define OFF_WIH1    6979584ull
#define OFF_WHH1    10223616ull
#define OFF_FREQ    13467648ull
#define OFF_ATTNOUT 13631488ull
#define OFF_PRE     14712832ull
#define OFF_SPL1    15794176ull
#define WPOOL_TOTAL 17821696ull

__device__ bf16 g_whi[WPOOL_TOTAL];
__device__ bf16 g_wlo[WPOOL_TOTAL];

// ---------------- activation split pool ----------------------------------------
#define OFFA_IN    0ull
#define OFFA_FRQ   4915200ull
#define OFFA_FEAT  7413760ull
#define OFFA_SEQ   23904256ull
#define OFFA_OBAR  56344576ull
#define OFFA_H0    56614912ull
#define OFFA_H1    56885248ull
#define OFFA_HID   57155584ull
#define OFFA_XT    57425920ull
#define APOOL_TOTAL 57466880ull

__device__ bf16 g_ahi[APOOL_TOTAL];
__device__ bf16 g_alo[APOOL_TOTAL];

// ---------------- scratch -------------------------------------------------------
__device__ float g_big[(size_t)BB * TS * GG];
__device__ float g_seq[(size_t)BB * TS * HH];
__device__ float g_in [(size_t)BB * TS * DD];
__device__ float g_frq[(size_t)BB * NF * DD];
__device__ float g_cosm[NF * TS];
__device__ float g_obar[BB * HH];
__device__ float g_mctx[BB * HH];
__device__ float g_h0[BB * HH];
__device__ float g_h1[BB * HH];
__device__ float g_ghp[(size_t)4 * BB * GG];
__device__ float g_gxp[(size_t)4 * BB * GG];
__device__ float g_prep[(size_t)8 * BB * HH];
__device__ float g_splp[(size_t)8 * BB * NJ * 128];
__device__ float g_z1[BB * NJ * 128];
__device__ float g_p6[BB * NJ * 6];

// ---------------- software grid barrier (nanosleep backoff) ----------------------
__device__ unsigned g_barcnt = 0;
__device__ unsigned g_barsense = 0;

__device__ __forceinline__ void grid_bar() {
    __syncthreads();
    if (threadIdx.x == 0) {
        unsigned my = *(volatile unsigned*)&g_barsense;
        __threadfence();
        unsigned arrived = atomicAdd(&g_barcnt, 1u);
        if (arrived == NBLK - 1) {
            atomicExch(&g_barcnt, 0u);
            __threadfence();
            atomicExch(&g_barsense, my ^ 1u);
        } else {
            while (*(volatile unsigned*)&g_barsense == my) { __nanosleep(64); }
            __threadfence();
        }
    }
    __syncthreads();
}

// ---------------- cp.async -------------------------------------------------------
__device__ __forceinline__ void cp16(bf16* dst, const bf16* src) {
    unsigned saddr = (unsigned)__cvta_generic_to_shared(dst);
    asm volatile("cp.async.cg.shared.global [%0], [%1], 16;\n" :: "r"(saddr), "l"(src));
}
#define CP_COMMIT() asm volatile("cp.async.commit_group;\n" ::: "memory")
#define CP_WAIT1()  asm volatile("cp.async.wait_group 1;\n" ::: "memory")
#define CP_WAIT0()  asm volatile("cp.async.wait_group 0;\n" ::: "memory")

// staging: A 128x32 + W 128x32, hi/lo (4 arrays)
__device__ __forceinline__ void stage_load(
    bf16* sb, const bf16* __restrict__ Ahi, const bf16* __restrict__ Alo,
    const bf16* __restrict__ Whi, const bf16* __restrict__ Wlo,
    int m0, int n0, int k0, int KP, int tid)
{
    #pragma unroll
    for (int it = 0; it < 2; it++) {
        int slot = tid + it * 256;
        int rw = slot >> 2;
        int col = (slot & 3) << 3;
        size_t aoff = (size_t)(m0 + rw) * KP + k0 + col;
        size_t woff = (size_t)(n0 + rw) * KP + k0 + col;
        int so = rw * 40 + col;
        cp16(sb + so,           Ahi + aoff);
        cp16(sb + SOFF_AL + so, Alo + aoff);
        cp16(sb + SOFF_WH + so, Whi + woff);
        cp16(sb + SOFF_WL + so, Wlo + woff);
    }
}

__device__ __forceinline__ void mma_stage(
    const bf16* sb, int wm, int wn,
    wmma::fragment<wmma::accumulator, 16, 16, 16, float> (&acc)[2][4])
{
    #pragma unroll
    for (int kk = 0; kk < 32; kk += 16) {
        wmma::fragment<wmma::matrix_a, 16, 16, 16, bf16, wmma::row_major> faH[2], faL[2];
        #pragma unroll
        for (int i = 0; i < 2; i++) {
            wmma::load_matrix_sync(faH[i], sb + (wm * 32 + i * 16) * 40 + kk, 40);
            wmma::load_matrix_sync(faL[i], sb + SOFF_AL + (wm * 32 + i * 16) * 40 + kk, 40);
        }
        #pragma unroll
        for (int j = 0; j < 4; j++) {
            wmma::fragment<wmma::matrix_b, 16, 16, 16, bf16, wmma::col_major> fbH, fbL;
            wmma::load_matrix_sync(fbH, sb + SOFF_WH + (wn * 64 + j * 16) * 40 + kk, 40);
            wmma::load_matrix_sync(fbL, sb + SOFF_WL + (wn * 64 + j * 16) * 40 + kk, 40);
            #pragma unroll
            for (int i = 0; i < 2; i++) {
                wmma::mma_sync(acc[i][j], faH[i], fbH, acc[i][j]);
                wmma::mma_sync(acc[i][j], faH[i], fbL, acc[i][j]);
                wmma::mma_sync(acc[i][j], faL[i], fbH, acc[i][j]);
            }
        }
    }
}

// shared GEMM body: one output tile over chunk range [c0, c0+nch), write to Cz
__device__ __forceinline__ void gemm_body(
    bf16* sm4, const bf16* Ahi, const bf16* Alo,
    const bf16* Whi, const bf16* Wlo, float* Cz,
    int m0, int n0, int c0, int nch, int KP, int N, int tid, int wm, int wn)
{
    wmma::fragment<wmma::accumulator, 16, 16, 16, float> acc[2][4];
    #pragma unroll
    for (int i = 0; i < 2; i++)
        #pragma unroll
        for (int j = 0; j < 4; j++)
            wmma::fill_fragment(acc[i][j], 0.0f);

    if (nch > 0) {
        stage_load(sm4, Ahi, Alo, Whi, Wlo, m0, n0, c0 << 5, KP, tid);
        CP_COMMIT();
    }
    for (int i = 0; i < nch; i++) {
        bf16* sb = sm4 + (i & 1) * SST;
        if (i + 1 < nch) {
            stage_load(sm4 + ((i + 1) & 1) * SST, Ahi, Alo, Whi, Wlo,
                       m0, n0, (c0 + i + 1) << 5, KP, tid);
            CP_COMMIT();
            CP_WAIT1();
        } else {
            CP_WAIT0();
        }
        __syncthreads();
        mma_stage(sb, wm, wn, acc);
        __syncthreads();
    }
    #pragma unroll
    for (int i = 0; i < 2; i++)
        #pragma unroll
        for (int j = 0; j < 4; j++)
            wmma::store_matrix_sync(
                Cz + (size_t)(m0 + wm * 32 + i * 16) * N + (n0 + wn * 64 + j * 16),
                acc[i][j], N, wmma::mem_row_major);
}

// ---------------- small utility kernels -----------------------------------------

__global__ void copy_inseq_kernel(const float* __restrict__ poses, float* __restrict__ dst) {
    int idx = blockIdx.x * 256 + threadIdx.x;
    if (idx >= BB * TS * DD) return;
    int d = idx % DD;
    int t = (idx / DD) % TS;
    int b = idx / (TS * DD);
    dst[idx] = poses[((size_t)b * (TS + PREDN) + t) * DD + d];
}

__global__ void build_cos_kernel(float* __restrict__ cosm) {
    int idx = blockIdx.x * 256 + threadIdx.x;
    if (idx >= NF * TS) return;
    int f = idx / TS, t = idx % TS;
    cosm[idx] = (float)cos(2.0 * 3.14159265358979323846 * (double)(f * t) / (double)TS);
}

__global__ void freq_kernel(const float* __restrict__ inseq, const float* __restrict__ cosm,
                            float* __restrict__ freq) {
    int b = blockIdx.x, f = blockIdx.y, d = threadIdx.x;
    if (d >= DD) return;
    const float* xp = inseq + (size_t)b * TS * DD + d;
    const float* cp = cosm + f * TS;
    float s = 0.f;
    #pragma unroll 4
    for (int t = 0; t < TS; t++) s += cp[t] * xp[(size_t)t * DD];
    freq[((size_t)b * NF + f) * DD + d] = s;
}

// ---------------- splitters -------------------------------------------------------
__global__ void split_w_kernel(const float* __restrict__ W, const float* __restrict__ bias,
                               bf16* __restrict__ hi, bf16* __restrict__ lo,
                               int N, int K, int KP) {
    size_t idx = (size_t)blockIdx.x * 256 + threadIdx.x;
    if (idx >= (size_t)N * KP) return;
    int k = (int)(idx % KP);
    int n = (int)(idx / KP);
    float v = 0.f;
    if (k < K) v = W[(size_t)n * K + k];
    else if (k == K) v = bias[n];
    bf16 h = __float2bfloat16(v);
    hi[idx] = h;
    lo[idx] = __float2bfloat16(v - __bfloat162float(h));
}

__global__ void split_a_kernel(const float* __restrict__ A,
                               bf16* __restrict__ hi, bf16* __restrict__ lo,
                               int M, int K, int KP) {
    size_t idx = (size_t)blockIdx.x * 256 + threadIdx.x;
    if (idx >= (size_t)M * KP) return;
    int k = (int)(idx % KP);
    int m = (int)(idx / KP);
    float v = 0.f;
    if (k < K) v = A[(size_t)m * K + k];
    else if (k == K) v = 1.0f;
    bf16 h = __float2bfloat16(v);
    hi[idx] = h;
    lo[idx] = __float2bfloat16(v - __bfloat162float(h));
}

// full init (data cols zero + ones col) -- for h buffers read before first write
__global__ void zero_split_kernel(bf16* __restrict__ hi, bf16* __restrict__ lo,
                                  int M, int K, int KP) {
    size_t idx = (size_t)blockIdx.x * 256 + threadIdx.x;
    if (idx >= (size_t)M * KP) return;
    int k = (int)(idx % KP);
    float v = (k == K) ? 1.0f : 0.0f;
    hi[idx] = __float2bfloat16(v);
    lo[idx] = __float2bfloat16(0.0f);
}

// pad-only init (cols K..KP-1) -- data cols are fully written by producers
__global__ void pad_init_kernel(bf16* __restrict__ hi, bf16* __restrict__ lo,
                                int M, int K, int KP) {
    int PAD = KP - K;
    size_t idx = (size_t)blockIdx.x * 256 + threadIdx.x;
    if (idx >= (size_t)M * PAD) return;
    int p = (int)(idx % PAD);
    int m = (int)(idx / PAD);
    size_t o = (size_t)m * KP + K + p;
    float v = (p == 0) ? 1.0f : 0.0f;
    hi[o] = __float2bfloat16(v);
    lo[o] = __float2bfloat16(0.0f);
}

// ---------------- gemm4 (batch / decode single) -------------------------------------
__global__ __launch_bounds__(256, 2) void gemm4_kernel(
    const bf16* __restrict__ Ahi, const bf16* __restrict__ Alo,
    const bf16* __restrict__ Whi, const bf16* __restrict__ Wlo,
    float* __restrict__ C, int M, int N, int KP)
{
    extern __shared__ __align__(16) bf16 sm4[];
    int tid = threadIdx.x;
    int warp = tid >> 5;
    int wm = warp >> 1, wn = warp & 1;
    int m0 = blockIdx.y * 128, n0 = blockIdx.x * 128;

    int CH  = KP >> 5;
    int cpz = (CH + gridDim.z - 1) / gridDim.z;
    int c0  = blockIdx.z * cpz;
    int c1  = c0 + cpz; if (c1 > CH) c1 = CH;

    gemm_body(sm4, Ahi, Alo, Whi, Wlo, C + (size_t)blockIdx.z * M * N,
              m0, n0, c0, c1 - c0, KP, N, tid, wm, wn);
}

// ---------------- dual gemm: two independent M=256,N=3072 problems in one launch ----
__global__ __launch_bounds__(256, 2) void gemm4_dual_kernel(
    const bf16* __restrict__ Ah0, const bf16* __restrict__ Al0,
    const bf16* __restrict__ Wh0, const bf16* __restrict__ Wl0,
    float* __restrict__ C0, int KP0, int sk0,
    const bf16* __restrict__ Ah1, const bf16* __restrict__ Al1,
    const bf16* __restrict__ Wh1, const bf16* __restrict__ Wl1,
    float* __restrict__ C1, int KP1)
{
    extern __shared__ __align__(16) bf16 sm4[];
    int tid = threadIdx.x;
    int warp = tid >> 5;
    int wm = warp >> 1, wn = warp & 1;
    int m0 = blockIdx.y * 128, n0 = blockIdx.x * 128;

    const bf16 *Ahi, *Alo, *Whi, *Wlo;
    float* C;
    int KP, sk, zz;
    int z = blockIdx.z;
    if (z < sk0) {
        Ahi = Ah0; Alo = Al0; Whi = Wh0; Wlo = Wl0; C = C0; KP = KP0;
        sk = sk0; zz = z;
    } else {
        Ahi = Ah1; Alo = Al1; Whi = Wh1; Wlo = Wl1; C = C1; KP = KP1;
        sk = gridDim.z - sk0; zz = z - sk0;
    }
    int CH  = KP >> 5;
    int cpz = (CH + sk - 1) / sk;
    int c0  = zz * cpz;
    int c1  = c0 + cpz; if (c1 > CH) c1 = CH;

    gemm_body(sm4, Ahi, Alo, Whi, Wlo, C + (size_t)zz * (BB * GG),
              m0, n0, c0, c1 - c0, KP, GG, tid, wm, wn);
}

// ---------------- persistent GRU recurrence (R7 streamed form) --------------------
__global__ __launch_bounds__(256, 1) void gru_persist_kernel(
    const float* __restrict__ gi,          // (B, TS, GG), bih fused
    const bf16* __restrict__ Whi,          // (GG, KP1024), bhh in col HH
    const bf16* __restrict__ Wlo,
    float* __restrict__ h,                 // (B, HH) fp32, pre-zeroed
    bf16* __restrict__ hhi,                // (B, KP1024), pre-inited
    bf16* __restrict__ hlo,
    float* __restrict__ ghp,               // (3, B, GG) partials
    bf16* __restrict__ seqhi,              // (B, TS, KP1024) or null
    bf16* __restrict__ seqlo,
    int nsteps)
{
    extern __shared__ __align__(16) bf16 sm4[];
    int tid = threadIdx.x;
    int warp = tid >> 5;
    int wm = warp >> 1, wn = warp & 1;
    int tile  = blockIdx.x % 48;
    int slice = blockIdx.x / 48;           // 0..2
    int m0 = (tile / 24) * 128;
    int n0 = (tile % 24) * 128;
    const int c0 = slice * 11;

    for (int t = 0; t < nsteps; t++) {
        gemm_body(sm4, hhi, hlo, Whi, Wlo, ghp + (size_t)slice * (BB * GG),
                  m0, n0, c0, 11, KP1024, GG, tid, wm, wn);

        __threadfence();
        grid_bar();

        // gate math
        for (int idx = blockIdx.x * 256 + tid; idx < BB * HH; idx += NBLK * 256) {
            int b = idx >> 10, j = idx & 1023;
            const float* gib = gi + ((size_t)b * TS + t) * GG;
            float ir = gib[j], iz = gib[HH + j], inn = gib[2 * HH + j];
            float hr = 0.f, hz = 0.f, hn = 0.f;
            #pragma unroll
            for (int s = 0; s < 3; s++) {
                const float* g = ghp + (size_t)s * (BB * GG) + (size_t)b * GG;
                hr += __ldcg(&g[j]);
                hz += __ldcg(&g[HH + j]);
                hn += __ldcg(&g[2 * HH + j]);
            }
            float r = 1.f / (1.f + expf(-(ir + hr)));
            float z = 1.f / (1.f + expf(-(iz + hz)));
            float n = tanhf(inn + r * hn);
            float hp = __ldcg(&h[idx]);
            float hnew = (1.f - z) * n + z * hp;
            h[idx] = hnew;
            bf16 hb = __float2bfloat16(hnew);
            bf16 lb = __float2bfloat16(hnew - __bfloat162float(hb));
            size_t ho = (size_t)b * KP1024 + j;
            hhi[ho] = hb;
            hlo[ho] = lb;
            if (seqhi) {
                size_t so = ((size_t)b * TS + t) * KP1024 + j;
                seqhi[so] = hb;
                seqlo[so] = lb;
            }
        }
        __threadfence();
        grid_bar();
    }
}

// ---------------- attention --------------------------------------------------------
__global__ __launch_bounds__(256) void attention_kernel(const float* __restrict__ qkv,
                                                        float* __restrict__ o) {
    extern __shared__ float sm[];
    float* kv = sm;
    float* sc = sm + NF * DHD;
    int b = blockIdx.x >> 2;
    int h = blockIdx.x & 3;
    int tid = threadIdx.x;
    int lane = tid & 31, w = tid >> 5;
    const float* base = qkv + (size_t)b * NF * GG + h * DHD;

    for (int idx = tid; idx < NF * DHD; idx += 256) {
        int t = idx >> 8, d = idx & 255;
        kv[idx] = base[(size_t)t * GG + HH + d];
    }
    __syncthreads();
    for (int i = w; i < NF; i += 8) {
        float q[8];
        const float* qp = base + (size_t)i * GG;
        #pragma unroll
        for (int c = 0; c < 8; c++) q[c] = qp[lane + 32 * c];
        for (int j = 0; j < NF; j++) {
            const float* kp = kv + j * DHD;
            float s = 0.f;
            #pragma unroll
            for (int c = 0; c < 8; c++) s += q[c] * kp[lane + 32 * c];
            #pragma unroll
            for (int off = 16; off; off >>= 1) s += __shfl_xor_sync(0xffffffffu, s, off);
            if (lane == 0) sc[i * 64 + j] = s * 0.0625f;
        }
    }
    __syncthreads();
    for (int i = w; i < NF; i += 8) {
        float v0 = (lane < NF) ? sc[i * 64 + lane] : -1e30f;
        float v1 = (lane + 32 < NF) ? sc[i * 64 + lane + 32] : -1e30f;
        float m = fmaxf(v0, v1);
        #pragma unroll
        for (int off = 16; off; off >>= 1) m = fmaxf(m, __shfl_xor_sync(0xffffffffu, m, off));
        float e0 = (lane < NF) ? expf(v0 - m) : 0.f;
        float e1 = (lane + 32 < NF) ? expf(v1 - m) : 0.f;
        float ss = e0 + e1;
        #pragma unroll
        for (int off = 16; off; off >>= 1) ss += __shfl_xor_sync(0xffffffffu, ss, off);
        float inv = 1.f / ss;
        if (lane < NF) sc[i * 64 + lane] = e0 * inv;
        if (lane + 32 < NF) sc[i * 64 + lane + 32] = e1 * inv;
    }
    __syncthreads();
    for (int idx = tid; idx < NF * DHD; idx += 256) {
        int t = idx >> 8, d = idx & 255;
        kv[idx] = base[(size_t)t * GG + 2 * HH + d];
    }
    __syncthreads();
    float acc[NF];
    #pragma unroll
    for (int i = 0; i < NF; i++) acc[i] = 0.f;
    int d = tid;
    for (int j = 0; j < NF; j++) {
        float vv = kv[j * DHD + d];
        #pragma unroll
        for (int i = 0; i < NF; i++) acc[i] += sc[i * 64 + j] * vv;
    }
    float* ob = o + (size_t)b * NF * HH + h * DHD + d;
    #pragma unroll
    for (int i = 0; i < NF; i++) ob[(size_t)i * HH] = acc[i];
}

__global__ void mean61_kernel(const float* __restrict__ o, float* __restrict__ obar) {
    int idx = blockIdx.x * 256 + threadIdx.x;
    if (idx >= BB * HH) return;
    int b = idx >> 10, c = idx & 1023;
    const float* p = o + (size_t)b * NF * HH + c;
    float s = 0.f;
    for (int t = 0; t < NF; t++) s += p[(size_t)t * HH];
    obar[idx] = s * (1.f / (float)NF);
}

// ---------------- decode gate -------------------------------------------------------
__global__ void gru_gate2(const float* __restrict__ gxp, int gx_sk,
                          const float* __restrict__ ghp, int gh_sk,
                          float* __restrict__ h,
                          bf16* __restrict__ hhi, bf16* __restrict__ hlo) {
    int idx = blockIdx.x * 256 + threadIdx.x;
    if (idx >= BB * HH) return;
    int b = idx >> 10, j = idx & 1023;
    float ir = 0.f, iz = 0.f, in = 0.f;
    for (int s = 0; s < gx_sk; s++) {
        const float* g = gxp + (size_t)s * (BB * GG) + (size_t)b * GG;
        ir += g[j]; iz += g[HH + j]; in += g[2 * HH + j];
    }
    float hr = 0.f, hz = 0.f, hn = 0.f;
    for (int s = 0; s < gh_sk; s++) {
        const float* g = ghp + (size_t)s * (BB * GG) + (size_t)b * GG;
        hr += g[j]; hz += g[HH + j]; hn += g[2 * HH + j];
    }
    float r = 1.f / (1.f + expf(-(ir + hr)));
    float z = 1.f / (1.f + expf(-(iz + hz)));
    float n = tanhf(in + r * hn);
    float hp = h[idx];
    float hnew = (1.f - z) * n + z * hp;
    h[idx] = hnew;
    bf16 hb = __float2bfloat16(hnew);
    size_t ho = (size_t)b * KP1024 + j;
    hhi[ho] = hb;
    hlo[ho] = __float2bfloat16(hnew - __bfloat162float(hb));
}

// ---------------- split-K reductions ------------------------------------------------
__global__ void reduce_act_kernel(const float* __restrict__ part, int sk, int mn,
                                  float* __restrict__ out) {
    int idx = blockIdx.x * 256 + threadIdx.x;
    if (idx >= mn) return;
    float s = 0.f;
    for (int i = 0; i < sk; i++) s += part[(size_t)i * mn + idx];
    out[idx] = fmaxf(s, 0.f);
}

__global__ void reduce_split_kernel(const float* __restrict__ part, int sk,
                                    const float* __restrict__ addend,
                                    bf16* __restrict__ hi, bf16* __restrict__ lo) {
    int idx = blockIdx.x * 256 + threadIdx.x;
    if (idx >= BB * HH) return;
    int b = idx >> 10, j = idx & 1023;
    float s = 0.f;
    for (int i = 0; i < sk; i++) s += part[(size_t)i * (BB * HH) + idx];
    s = fmaxf(s, 0.f) + addend[idx];
    bf16 hb = __float2bfloat16(s);
    size_t o = (size_t)b * KP1024 + j;
    hi[o] = hb;
    lo[o] = __float2bfloat16(s - __bfloat162float(hb));
}

// ---------------- decode init ---------------------------------------------------------
__global__ void init_decode(const float* __restrict__ inseq,
                            bf16* __restrict__ xthi, bf16* __restrict__ xtlo,
                            float* __restrict__ p6) {
    int idx = blockIdx.x * 256 + threadIdx.x;
    if (idx >= BB * KP135) return;
    int b = idx / KP135, d = idx % KP135;
    const float* last = inseq + ((size_t)b * TS + (TS - 1)) * DD;
    float v = 0.f;
    if (d < DD) v = last[d];
    else if (d == DD) v = 1.0f;
    bf16 hb = __float2bfloat16(v);
    xthi[idx] = hb;
    xtlo[idx] = __float2bfloat16(v - __bfloat162float(hb));
    if (d < NJ * 6) {
        int j = d / 6, o = d % 6;
        int src = (o < 3) ? (j * 9 + o * 3) : (j * 9 + (o - 3) * 3 + 1);
        p6[(size_t)b * 90 + d] = last[src];
    }
}

// ---------------- spl head layer2 + rot6d -------------------------------------------
__global__ __launch_bounds__(192) void spl2_rot(const float* __restrict__ z1,
                                                const float* __restrict__ w2,
                                                const float* __restrict__ b2,
                                                float* __restrict__ p6,
                                                bf16* __restrict__ xthi,
                                                bf16* __restrict__ xtlo,
                                                float* __restrict__ out, int step) {
    int bj = blockIdx.x;
    int b = bj / NJ, j = bj % NJ;
    int w = threadIdx.x >> 5, lane = threadIdx.x & 31;
    __shared__ float v6[6];
    const float* zz = z1 + (size_t)b * (NJ * 128) + j * 128;
    const float* ww = w2 + ((size_t)j * 6 + w) * 128;
    float s = 0.f;
    #pragma unroll
    for (int c = 0; c < 4; c++) s += zz[lane + 32 * c] * ww[lane + 32 * c];
    #pragma unroll
    for (int off = 16; off; off >>= 1) s += __shfl_xor_sync(0xffffffffu, s, off);
    if (lane == 0)
        v6[w] = p6[(size_t)b * 90 + j * 6 + w] + s + b2[j * 6 + w];
    __syncthreads();
    if (threadIdx.x < 6) {
        float v = v6[threadIdx.x];
        p6[(size_t)b * 90 + j * 6 + threadIdx.x] = v;
        out[((size_t)b * PREDN + step) * 90 + j * 6 + threadIdx.x] = v;
    }
    if (threadIdx.x == 0) {
        float a1x = v6[0], a2x = v6[1], a1y = v6[2], a2y = v6[3], a1z = v6[4], a2z = v6[5];
        float n1 = fmaxf(sqrtf(a1x*a1x + a1y*a1y + a1z*a1z), 1e-12f);
        float b1x = a1x / n1, b1y = a1y / n1, b1z = a1z / n1;
        float dot = b1x*a2x + b1y*a2y + b1z*a2z;
        float ox = a2x - dot*b1x, oy = a2y - dot*b1y, oz = a2z - dot*b1z;
        float n2 = fmaxf(sqrtf(ox*ox + oy*oy + oz*oz), 1e-12f);
        float b2x = ox / n2, b2y = oy / n2, b2z = oz / n2;
        float b3x = b1y*b2z - b1z*b2y;
        float b3y = b1z*b2x - b1x*b2z;
        float b3z = b1x*b2y - b1y*b2x;
        float rm[9] = { b1x, b2x, b3x, b1y, b2y, b3y, b1z, b2z, b3z };
        size_t base = (size_t)b * KP135 + j * 9;
        #pragma unroll
        for (int c = 0; c < 9; c++) {
            bf16 hb = __float2bfloat16(rm[c]);
            xthi[base + c] = hb;
            xtlo[base + c] = __float2bfloat16(rm[c] - __bfloat162float(hb));
        }
    }
}

// ---------------- host orchestration --------------------------------------------------

static inline void gemm4(const bf16* ahi, const bf16* alo,
                         const bf16* whi, const bf16* wlo,
                         float* C, int M, int N, int KP, int sk) {
    dim3 g(N / 128, M / 128, sk);
    gemm4_kernel<<<g, 256, SMEM_BYTES>>>(ahi, alo, whi, wlo, C, M, N, KP);
}

static inline void gemm4_dual(const bf16* ah0, const bf16* al0,
                              const bf16* wh0, const bf16* wl0, float* c0, int kp0, int sk0,
                              const bf16* ah1, const bf16* al1,
                              const bf16* wh1, const bf16* wl1, float* c1, int kp1, int sk1) {
    dim3 g(GG / 128, BB / 128, sk0 + sk1);
    gemm4_dual_kernel<<<g, 256, SMEM_BYTES>>>(ah0, al0, wh0, wl0, c0, kp0, sk0,
                                              ah1, al1, wh1, wl1, c1, kp1);
}

static inline void splitw(const float* W, const float* bias,
                          bf16* hi, bf16* lo, int N, int K, int KP) {
    size_t n = (size_t)N * KP;
    split_w_kernel<<<(int)((n + 255) / 256), 256>>>(W, bias, hi, lo, N, K, KP);
}

static inline void splita(const float* A, bf16* hi, bf16* lo, int M, int K, int KP) {
    size_t n = (size_t)M * KP;
    split_a_kernel<<<(int)((n + 255) / 256), 256>>>(A, hi, lo, M, K, KP);
}

static inline void zerosplit(bf16* hi, bf16* lo, int M, int K, int KP) {
    size_t n = (size_t)M * KP;
    zero_split_kernel<<<(int)((n + 255) / 256), 256>>>(hi, lo, M, K, KP);
}

static inline void padinit(bf16* hi, bf16* lo, int M, int K, int KP) {
    size_t n = (size_t)M * (KP - K);
    pad_init_kernel<<<(int)((n + 255) / 256), 256>>>(hi, lo, M, K, KP);
}

extern "C" void kernel_launch(void* const* d_in, const int* in_sizes, int n_in,
                              void* d_out, int out_size) {
    const float* poses      = (const float*)d_in[0];
    const float* freq_w     = (const float*)d_in[1];
    const float* freq_b     = (const float*)d_in[2];
    const float* attn_in_w  = (const float*)d_in[3];
    const float* attn_in_b  = (const float*)d_in[4];
    const float* attn_out_w = (const float*)d_in[5];
    const float* attn_out_b = (const float*)d_in[6];
    const float* gru_wih0   = (const float*)d_in[7];
    const float* gru_whh0   = (const float*)d_in[8];
    const float* gru_bih0   = (const float*)d_in[9];
    const float* gru_bhh0   = (const float*)d_in[10];
    const float* gru_wih1   = (const float*)d_in[11];
    const float* gru_whh1   = (const float*)d_in[12];
    const float* gru_bih1   = (const float*)d_in[13];
    const float* gru_bhh1   = (const float*)d_in[14];
    const float* pre_w      = (const float*)d_in[15];
    const float* pre_b      = (const float*)d_in[16];
    const float* spl_w1     = (const float*)d_in[17];
    const float* spl_b1     = (const float*)d_in[18];
    const float* spl_w2     = (const float*)d_in[19];
    const float* spl_b2     = (const float*)d_in[20];
    float* out = (float*)d_out;

    float *pBig, *pSeq, *pIn, *pFrq, *pCos, *pObar, *pMctx, *pH0, *pH1,
          *pGhp, *pGxp, *pPrep, *pSplp, *pZ1, *pP6;
    bf16 *pWhi, *pWlo, *pAhi, *pAlo;
    cudaGetSymbolAddress((void**)&pBig, g_big);
    cudaGetSymbolAddress((void**)&pSeq, g_seq);
    cudaGetSymbolAddress((void**)&pIn,  g_in);
    cudaGetSymbolAddress((void**)&pFrq, g_frq);
    cudaGetSymbolAddress((void**)&pCos, g_cosm);
    cudaGetSymbolAddress((void**)&pObar, g_obar);
    cudaGetSymbolAddress((void**)&pMctx, g_mctx);
    cudaGetSymbolAddress((void**)&pH0, g_h0);
    cudaGetSymbolAddress((void**)&pH1, g_h1);
    cudaGetSymbolAddress((void**)&pGhp, g_ghp);
    cudaGetSymbolAddress((void**)&pGxp, g_gxp);
    cudaGetSymbolAddress((void**)&pPrep, g_prep);
    cudaGetSymbolAddress((void**)&pSplp, g_splp);
    cudaGetSymbolAddress((void**)&pZ1, g_z1);
    cudaGetSymbolAddress((void**)&pP6, g_p6);
    cudaGetSymbolAddress((void**)&pWhi, g_whi);
    cudaGetSymbolAddress((void**)&pWlo, g_wlo);
    cudaGetSymbolAddress((void**)&pAhi, g_ahi);
    cudaGetSymbolAddress((void**)&pAlo, g_alo);

    cudaFuncSetAttribute(gemm4_kernel, cudaFuncAttributeMaxDynamicSharedMemorySize, SMEM_BYTES);
    cudaFuncSetAttribute(gemm4_dual_kernel, cudaFuncAttributeMaxDynamicSharedMemorySize, SMEM_BYTES);
    cudaFuncSetAttribute(gru_persist_kernel, cudaFuncAttributeMaxDynamicSharedMemorySize, SMEM_BYTES);

    float* qkv   = pBig;
    float* attno = pBig + (size_t)BB * NF * GG;
    float* gi    = pBig;
    float* feat  = pSeq;

    const int BF = BB * NF;
    const int BT = BB * TS;

    // ---- one-time weight splits ----
    splitw(attn_in_w, attn_in_b, pWhi + OFF_ATTNIN,  pWlo + OFF_ATTNIN,  GG, HH, KP1024);
    splitw(gru_wih0,  gru_bih0,  pWhi + OFF_WIH0,    pWlo + OFF_WIH0,    GG, DD, KP135);
    splitw(gru_whh0,  gru_bhh0,  pWhi + OFF_WHH0,    pWlo + OFF_WHH0,    GG, HH, KP1024);
    splitw(gru_wih1,  gru_bih1,  pWhi + OFF_WIH1,    pWlo + OFF_WIH1,    GG, HH, KP1024);
    splitw(gru_whh1,  gru_bhh1,  pWhi + OFF_WHH1,    pWlo + OFF_WHH1,    GG, HH, KP1024);
    splitw(freq_w,    freq_b,    pWhi + OFF_FREQ,    pWlo + OFF_FREQ,    HH, DD, KP135);
    splitw(attn_out_w,attn_out_b,pWhi + OFF_ATTNOUT, pWlo + OFF_ATTNOUT, HH, HH, KP1024);
    splitw(pre_w,     pre_b,     pWhi + OFF_PRE,     pWlo + OFF_PRE,     HH, HH, KP1024);
    splitw(spl_w1,    spl_b1,    pWhi + OFF_SPL1,    pWlo + OFF_SPL1,    NJ*128, HH, KP1024);

    // ---- activation split buffer init ----
    padinit(pAhi + OFFA_SEQ, pAlo + OFFA_SEQ, BT, HH, KP1024);
    zerosplit(pAhi + OFFA_H0,  pAlo + OFFA_H0,  BB, HH, KP1024);
    zerosplit(pAhi + OFFA_H1,  pAlo + OFFA_H1,  BB, HH, KP1024);
    padinit(pAhi + OFFA_HID, pAlo + OFFA_HID, BB, HH, KP1024);

    // ---- frequency attention branch ----
    copy_inseq_kernel<<<(BB*TS*DD + 255) / 256, 256>>>(poses, pIn);
    build_cos_kernel<<<(NF*TS + 255) / 256, 256>>>(pCos);
    freq_kernel<<<dim3(BB, NF), 160>>>(pIn, pCos, pFrq);
    splita(pFrq, pAhi + OFFA_FRQ, pAlo + OFFA_FRQ, BF, DD, KP135);
    gemm4(pAhi + OFFA_FRQ, pAlo + OFFA_FRQ, pWhi + OFF_FREQ, pWlo + OFF_FREQ,
          feat, BF, HH, KP135, 1);
    splita(feat, pAhi + OFFA_FEAT, pAlo + OFFA_FEAT, BF, HH, KP1024);
    gemm4(pAhi + OFFA_FEAT, pAlo + OFFA_FEAT, pWhi + OFF_ATTNIN, pWlo + OFF_ATTNIN,
          qkv, BF, GG, KP1024, 1);

    int smem_attn = (NF * DHD + NF * 64) * (int)sizeof(float);
    cudaFuncSetAttribute(attention_kernel, cudaFuncAttributeMaxDynamicSharedMemorySize, smem_attn);
    attention_kernel<<<BB * NHEAD, 256, smem_attn>>>(qkv, attno);
    mean61_kernel<<<(BB*HH + 255) / 256, 256>>>(attno, pObar);
    splita(pObar, pAhi + OFFA_OBAR, pAlo + OFFA_OBAR, BB, HH, KP1024);
    gemm4(pAhi + OFFA_OBAR, pAlo + OFFA_OBAR, pWhi + OFF_ATTNOUT, pWlo + OFF_ATTNOUT,
          pMctx, BB, HH, KP1024, 1);

    // ---- GRU layer 0 (persistent recurrence, R7 streamed form) ----
    splita(pIn, pAhi + OFFA_IN, pAlo + OFFA_IN, BT, DD, KP135);
    gemm4(pAhi + OFFA_IN, pAlo + OFFA_IN, pWhi + OFF_WIH0, pWlo + OFF_WIH0,
          gi, BT, GG, KP135, 1);
    cudaMemsetAsync(pH0, 0, (size_t)BB * HH * sizeof(float));
    gru_persist_kernel<<<NBLK, 256, SMEM_BYTES>>>(gi, pWhi + OFF_WHH0, pWlo + OFF_WHH0,
                                      pH0, pAhi + OFFA_H0, pAlo + OFFA_H0, pGhp,
                                      pAhi + OFFA_SEQ, pAlo + OFFA_SEQ, TS);

    // ---- GRU layer 1 ----
    gemm4(pAhi + OFFA_SEQ, pAlo + OFFA_SEQ, pWhi + OFF_WIH1, pWlo + OFF_WIH1,
          gi, BT, GG, KP1024, 1);
    cudaMemsetAsync(pH1, 0, (size_t)BB * HH * sizeof(float));
    gru_persist_kernel<<<NBLK, 256, SMEM_BYTES>>>(gi, pWhi + OFF_WHH1, pWlo + OFF_WHH1,
                                      pH1, pAhi + OFFA_H1, pAlo + OFFA_H1, pGhp,
                                      nullptr, nullptr, TS);

    // ---- autoregressive decode (dual-GEMM batched pairs) ----
    init_decode<<<(BB*KP135 + 255) / 256, 256>>>(pIn, pAhi + OFFA_XT, pAlo + OFFA_XT, pP6);
    for (int s = 0; s < PREDN; s++) {
        gemm4_dual(pAhi + OFFA_XT, pAlo + OFFA_XT, pWhi + OFF_WIH0, pWlo + OFF_WIH0,
                   pGxp, KP135, 2,
                   pAhi + OFFA_H0, pAlo + OFFA_H0, pWhi + OFF_WHH0, pWlo + OFF_WHH0,
                   pGhp, KP1024, 4);
        gru_gate2<<<(BB*HH)/256, 256>>>(pGxp, 2, pGhp, 4, pH0,
                                        pAhi + OFFA_H0, pAlo + OFFA_H0);

        gemm4_dual(pAhi + OFFA_H0, pAlo + OFFA_H0, pWhi + OFF_WIH1, pWlo + OFF_WIH1,
                   pGxp, KP1024, 4,
                   pAhi + OFFA_H1, pAlo + OFFA_H1, pWhi + OFF_WHH1, pWlo + OFF_WHH1,
                   pGhp, KP1024, 4);
        gru_gate2<<<(BB*HH)/256, 256>>>(pGxp, 4, pGhp, 4, pH1,
                                        pAhi + OFFA_H1, pAlo + OFFA_H1);

        gemm4(pAhi + OFFA_H1, pAlo + OFFA_H1, pWhi + OFF_PRE, pWlo + OFF_PRE,
              pPrep, BB, HH, KP1024, 8);
        reduce_split_kernel<<<(BB*HH + 255)/256, 256>>>(pPrep, 8, pMctx,
                                                        pAhi + OFFA_HID, pAlo + OFFA_HID);

        gemm4(pAhi + OFFA_HID, pAlo + OFFA_HID, pWhi + OFF_SPL1, pWlo + OFF_SPL1,
              pSplp, BB, NJ*128, KP1024, 8);
        reduce_act_kernel<<<(BB*NJ*128 + 255)/256, 256>>>(pSplp, 8, BB*NJ*128, pZ1);

        spl2_rot<<<BB * NJ, 192>>>(pZ1, spl_w2, spl_b2, pP6,
                                   pAhi + OFFA_XT, pAlo + OFFA_XT, out, s);
    }
}

// round 12
// speedup vs baseline: 1.1280x; 1.0118x over previous
#include <cuda_runtime.h>
#include <cuda_bf16.h>
#include <mma.h>
#include <math.h>

using namespace nvcuda;

#define BB    256
#define TS    120
#define PREDN 24
#define NJ    15
#define HH    1024
#define DD    135
#define NF    61
#define GG    3072
#define NHEAD 4
#define DHD   256

#define KP1024 1056
#define KP135  160

#define NBLK  144       // persistent grid size (<= 148 SMs -> co-resident)

// ---- gemm smem staging (4 arrays x 128x40) ----
#define SOFF_AL 5120
#define SOFF_WH 10240
#define SOFF_WL 15360
#define SST     20480                   // bf16 per stage
#define SMEM_BYTES (2 * SST * 2)        // 81920 B

typedef __nv_bfloat16 bf16;

// ---------------- weight split pools ------------------------------------------
#define OFF_ATTNIN  0ull
#define OFF_WIH0    3244032ull
#define OFF_WHH0    3735552ull
#define OFF_WIH1    6979584ull
#define OFF_WHH1    10223616ull
#define OFF_FREQ    13467648ull
#define OFF_ATTNOUT 13631488ull
#define OFF_PRE     14712832ull
#define OFF_SPL1    15794176ull
#define WPOOL_TOTAL 17821696ull

__device__ bf16 g_whi[WPOOL_TOTAL];
__device__ bf16 g_wlo[WPOOL_TOTAL];

// ---------------- activation split pool ----------------------------------------
#define OFFA_IN    0ull
#define OFFA_FRQ   4915200ull
#define OFFA_FEAT  7413760ull
#define OFFA_SEQ   23904256ull
#define OFFA_OBAR  56344576ull
#define OFFA_H0    56614912ull
#define OFFA_H1    56885248ull
#define OFFA_HID   57155584ull
#define OFFA_XT    57425920ull
#define APOOL_TOTAL 57466880ull

__device__ bf16 g_ahi[APOOL_TOTAL];
__device__ bf16 g_alo[APOOL_TOTAL];

// ---------------- scratch -------------------------------------------------------
__device__ float g_big[(size_t)BB * TS * GG];
__device__ float g_seq[(size_t)BB * TS * HH];
__device__ float g_in [(size_t)BB * TS * DD];
__device__ float g_frq[(size_t)BB * NF * DD];
__device__ float g_cosm[NF * TS];
__device__ float g_obar[BB * HH];
__device__ float g_mctx[BB * HH];
__device__ float g_h0[BB * HH];
__device__ float g_h1[BB * HH];
__device__ float g_ghp[(size_t)4 * BB * GG];
__device__ float g_gxp[(size_t)4 * BB * GG];
__device__ float g_prep[(size_t)8 * BB * HH];
__device__ float g_splp[(size_t)8 * BB * NJ * 128];
__device__ float g_z1[BB * NJ * 128];
__device__ float g_p6[BB * NJ * 6];

// ---------------- software grid barrier (plain hot spin -- R7 proven) -------------
__device__ unsigned g_barcnt = 0;
__device__ unsigned g_barsense = 0;

__device__ __forceinline__ void grid_bar() {
    __syncthreads();
    if (threadIdx.x == 0) {
        unsigned my = *(volatile unsigned*)&g_barsense;
        __threadfence();
        unsigned arrived = atomicAdd(&g_barcnt, 1u);
        if (arrived == NBLK - 1) {
            atomicExch(&g_barcnt, 0u);
            __threadfence();
            atomicExch(&g_barsense, my ^ 1u);
        } else {
            while (*(volatile unsigned*)&g_barsense == my) { }
            __threadfence();
        }
    }
    __syncthreads();
}

// ---------------- cp.async -------------------------------------------------------
__device__ __forceinline__ void cp16(bf16* dst, const bf16* src) {
    unsigned saddr = (unsigned)__cvta_generic_to_shared(dst);
    asm volatile("cp.async.cg.shared.global [%0], [%1], 16;\n" :: "r"(saddr), "l"(src));
}
#define CP_COMMIT() asm volatile("cp.async.commit_group;\n" ::: "memory")
#define CP_WAIT1()  asm volatile("cp.async.wait_group 1;\n" ::: "memory")
#define CP_WAIT0()  asm volatile("cp.async.wait_group 0;\n" ::: "memory")

// staging: A 128x32 + W 128x32, hi/lo (4 arrays)
__device__ __forceinline__ void stage_load(
    bf16* sb, const bf16* __restrict__ Ahi, const bf16* __restrict__ Alo,
    const bf16* __restrict__ Whi, const bf16* __restrict__ Wlo,
    int m0, int n0, int k0, int KP, int tid)
{
    #pragma unroll
    for (int it = 0; it < 2; it++) {
        int slot = tid + it * 256;
        int rw = slot >> 2;
        int col = (slot & 3) << 3;
        size_t aoff = (size_t)(m0 + rw) * KP + k0 + col;
        size_t woff = (size_t)(n0 + rw) * KP + k0 + col;
        int so = rw * 40 + col;
        cp16(sb + so,           Ahi + aoff);
        cp16(sb + SOFF_AL + so, Alo + aoff);
        cp16(sb + SOFF_WH + so, Whi + woff);
        cp16(sb + SOFF_WL + so, Wlo + woff);
    }
}

__device__ __forceinline__ void mma_stage(
    const bf16* sb, int wm, int wn,
    wmma::fragment<wmma::accumulator, 16, 16, 16, float> (&acc)[2][4])
{
    #pragma unroll
    for (int kk = 0; kk < 32; kk += 16) {
        wmma::fragment<wmma::matrix_a, 16, 16, 16, bf16, wmma::row_major> faH[2], faL[2];
        #pragma unroll
        for (int i = 0; i < 2; i++) {
            wmma::load_matrix_sync(faH[i], sb + (wm * 32 + i * 16) * 40 + kk, 40);
            wmma::load_matrix_sync(faL[i], sb + SOFF_AL + (wm * 32 + i * 16) * 40 + kk, 40);
        }
        #pragma unroll
        for (int j = 0; j < 4; j++) {
            wmma::fragment<wmma::matrix_b, 16, 16, 16, bf16, wmma::col_major> fbH, fbL;
            wmma::load_matrix_sync(fbH, sb + SOFF_WH + (wn * 64 + j * 16) * 40 + kk, 40);
            wmma::load_matrix_sync(fbL, sb + SOFF_WL + (wn * 64 + j * 16) * 40 + kk, 40);
            #pragma unroll
            for (int i = 0; i < 2; i++) {
                wmma::mma_sync(acc[i][j], faH[i], fbH, acc[i][j]);
                wmma::mma_sync(acc[i][j], faH[i], fbL, acc[i][j]);
                wmma::mma_sync(acc[i][j], faL[i], fbH, acc[i][j]);
            }
        }
    }
}

// shared GEMM body: one output tile over chunk range [c0, c0+nch), write to Cz
__device__ __forceinline__ void gemm_body(
    bf16* sm4, const bf16* Ahi, const bf16* Alo,
    const bf16* Whi, const bf16* Wlo, float* Cz,
    int m0, int n0, int c0, int nch, int KP, int N, int tid, int wm, int wn)
{
    wmma::fragment<wmma::accumulator, 16, 16, 16, float> acc[2][4];
    #pragma unroll
    for (int i = 0; i < 2; i++)
        #pragma unroll
        for (int j = 0; j < 4; j++)
            wmma::fill_fragment(acc[i][j], 0.0f);

    if (nch > 0) {
        stage_load(sm4, Ahi, Alo, Whi, Wlo, m0, n0, c0 << 5, KP, tid);
        CP_COMMIT();
    }
    for (int i = 0; i < nch; i++) {
        bf16* sb = sm4 + (i & 1) * SST;
        if (i + 1 < nch) {
            stage_load(sm4 + ((i + 1) & 1) * SST, Ahi, Alo, Whi, Wlo,
                       m0, n0, (c0 + i + 1) << 5, KP, tid);
            CP_COMMIT();
            CP_WAIT1();
        } else {
            CP_WAIT0();
        }
        __syncthreads();
        mma_stage(sb, wm, wn, acc);
        __syncthreads();
    }
    #pragma unroll
    for (int i = 0; i < 2; i++)
        #pragma unroll
        for (int j = 0; j < 4; j++)
            wmma::store_matrix_sync(
                Cz + (size_t)(m0 + wm * 32 + i * 16) * N + (n0 + wn * 64 + j * 16),
                acc[i][j], N, wmma::mem_row_major);
}

// ---------------- small utility kernels -----------------------------------------

__global__ void copy_inseq_kernel(const float* __restrict__ poses, float* __restrict__ dst) {
    int idx = blockIdx.x * 256 + threadIdx.x;
    if (idx >= BB * TS * DD) return;
    int d = idx % DD;
    int t = (idx / DD) % TS;
    int b = idx / (TS * DD);
    dst[idx] = poses[((size_t)b * (TS + PREDN) + t) * DD + d];
}

__global__ void build_cos_kernel(float* __restrict__ cosm) {
    int idx = blockIdx.x * 256 + threadIdx.x;
    if (idx >= NF * TS) return;
    int f = idx / TS, t = idx % TS;
    cosm[idx] = (float)cos(2.0 * 3.14159265358979323846 * (double)(f * t) / (double)TS);
}

__global__ void freq_kernel(const float* __restrict__ inseq, const float* __restrict__ cosm,
                            float* __restrict__ freq) {
    int b = blockIdx.x, f = blockIdx.y, d = threadIdx.x;
    if (d >= DD) return;
    const float* xp = inseq + (size_t)b * TS * DD + d;
    const float* cp = cosm + f * TS;
    float s = 0.f;
    #pragma unroll 4
    for (int t = 0; t < TS; t++) s += cp[t] * xp[(size_t)t * DD];
    freq[((size_t)b * NF + f) * DD + d] = s;
}

// ---------------- splitters -------------------------------------------------------
__global__ void split_w_kernel(const float* __restrict__ W, const float* __restrict__ bias,
                               bf16* __restrict__ hi, bf16* __restrict__ lo,
                               int N, int K, int KP) {
    size_t idx = (size_t)blockIdx.x * 256 + threadIdx.x;
    if (idx >= (size_t)N * KP) return;
    int k = (int)(idx % KP);
    int n = (int)(idx / KP);
    float v = 0.f;
    if (k < K) v = W[(size_t)n * K + k];
    else if (k == K) v = bias[n];
    bf16 h = __float2bfloat16(v);
    hi[idx] = h;
    lo[idx] = __float2bfloat16(v - __bfloat162float(h));
}

__global__ void split_a_kernel(const float* __restrict__ A,
                               bf16* __restrict__ hi, bf16* __restrict__ lo,
                               int M, int K, int KP) {
    size_t idx = (size_t)blockIdx.x * 256 + threadIdx.x;
    if (idx >= (size_t)M * KP) return;
    int k = (int)(idx % KP);
    int m = (int)(idx / KP);
    float v = 0.f;
    if (k < K) v = A[(size_t)m * K + k];
    else if (k == K) v = 1.0f;
    bf16 h = __float2bfloat16(v);
    hi[idx] = h;
    lo[idx] = __float2bfloat16(v - __bfloat162float(h));
}

// full init (data cols zero + ones col) -- for h buffers read before first write
__global__ void zero_split_kernel(bf16* __restrict__ hi, bf16* __restrict__ lo,
                                  int M, int K, int KP) {
    size_t idx = (size_t)blockIdx.x * 256 + threadIdx.x;
    if (idx >= (size_t)M * KP) return;
    int k = (int)(idx % KP);
    float v = (k == K) ? 1.0f : 0.0f;
    hi[idx] = __float2bfloat16(v);
    lo[idx] = __float2bfloat16(0.0f);
}

// pad-only init (cols K..KP-1) -- data cols are fully written by producers
__global__ void pad_init_kernel(bf16* __restrict__ hi, bf16* __restrict__ lo,
                                int M, int K, int KP) {
    int PAD = KP - K;
    size_t idx = (size_t)blockIdx.x * 256 + threadIdx.x;
    if (idx >= (size_t)M * PAD) return;
    int p = (int)(idx % PAD);
    int m = (int)(idx / PAD);
    size_t o = (size_t)m * KP + K + p;
    float v = (p == 0) ? 1.0f : 0.0f;
    hi[o] = __float2bfloat16(v);
    lo[o] = __float2bfloat16(0.0f);
}

// ---------------- gemm4 (batch / decode single) -------------------------------------
__global__ __launch_bounds__(256, 2) void gemm4_kernel(
    const bf16* __restrict__ Ahi, const bf16* __restrict__ Alo,
    const bf16* __restrict__ Whi, const bf16* __restrict__ Wlo,
    float* __restrict__ C, int M, int N, int KP)
{
    extern __shared__ __align__(16) bf16 sm4[];
    int tid = threadIdx.x;
    int warp = tid >> 5;
    int wm = warp >> 1, wn = warp & 1;
    int m0 = blockIdx.y * 128, n0 = blockIdx.x * 128;

    int CH  = KP >> 5;
    int cpz = (CH + gridDim.z - 1) / gridDim.z;
    int c0  = blockIdx.z * cpz;
    int c1  = c0 + cpz; if (c1 > CH) c1 = CH;

    gemm_body(sm4, Ahi, Alo, Whi, Wlo, C + (size_t)blockIdx.z * M * N,
              m0, n0, c0, c1 - c0, KP, N, tid, wm, wn);
}

// ---------------- dual gemm: two independent M=256,N=3072 problems in one launch ----
__global__ __launch_bounds__(256, 2) void gemm4_dual_kernel(
    const bf16* __restrict__ Ah0, const bf16* __restrict__ Al0,
    const bf16* __restrict__ Wh0, const bf16* __restrict__ Wl0,
    float* __restrict__ C0, int KP0, int sk0,
    const bf16* __restrict__ Ah1, const bf16* __restrict__ Al1,
    const bf16* __restrict__ Wh1, const bf16* __restrict__ Wl1,
    float* __restrict__ C1, int KP1)
{
    extern __shared__ __align__(16) bf16 sm4[];
    int tid = threadIdx.x;
    int warp = tid >> 5;
    int wm = warp >> 1, wn = warp & 1;
    int m0 = blockIdx.y * 128, n0 = blockIdx.x * 128;

    const bf16 *Ahi, *Alo, *Whi, *Wlo;
    float* C;
    int KP, sk, zz;
    int z = blockIdx.z;
    if (z < sk0) {
        Ahi = Ah0; Alo = Al0; Whi = Wh0; Wlo = Wl0; C = C0; KP = KP0;
        sk = sk0; zz = z;
    } else {
        Ahi = Ah1; Alo = Al1; Whi = Wh1; Wlo = Wl1; C = C1; KP = KP1;
        sk = gridDim.z - sk0; zz = z - sk0;
    }
    int CH  = KP >> 5;
    int cpz = (CH + sk - 1) / sk;
    int c0  = zz * cpz;
    int c1  = c0 + cpz; if (c1 > CH) c1 = CH;

    gemm_body(sm4, Ahi, Alo, Whi, Wlo, C + (size_t)zz * (BB * GG),
              m0, n0, c0, c1 - c0, KP, GG, tid, wm, wn);
}

// ---------------- persistent GRU recurrence (R7 streamed form) --------------------
__global__ __launch_bounds__(256, 1) void gru_persist_kernel(
    const float* __restrict__ gi,          // (B, TS, GG), bih fused
    const bf16* __restrict__ Whi,          // (GG, KP1024), bhh in col HH
    const bf16* __restrict__ Wlo,
    float* __restrict__ h,                 // (B, HH) fp32, pre-zeroed
    bf16* __restrict__ hhi,                // (B, KP1024), pre-inited
    bf16* __restrict__ hlo,
    float* __restrict__ ghp,               // (3, B, GG) partials
    bf16* __restrict__ seqhi,              // (B, TS, KP1024) or null
    bf16* __restrict__ seqlo,
    int nsteps)
{
    extern __shared__ __align__(16) bf16 sm4[];
    int tid = threadIdx.x;
    int warp = tid >> 5;
    int wm = warp >> 1, wn = warp & 1;
    int tile  = blockIdx.x % 48;
    int slice = blockIdx.x / 48;           // 0..2
    int m0 = (tile / 24) * 128;
    int n0 = (tile % 24) * 128;
    const int c0 = slice * 11;

    for (int t = 0; t < nsteps; t++) {
        gemm_body(sm4, hhi, hlo, Whi, Wlo, ghp + (size_t)slice * (BB * GG),
                  m0, n0, c0, 11, KP1024, GG, tid, wm, wn);

        __threadfence();
        grid_bar();

        // gate math
        for (int idx = blockIdx.x * 256 + tid; idx < BB * HH; idx += NBLK * 256) {
            int b = idx >> 10, j = idx & 1023;
            const float* gib = gi + ((size_t)b * TS + t) * GG;
            float ir = gib[j], iz = gib[HH + j], inn = gib[2 * HH + j];
            float hr = 0.f, hz = 0.f, hn = 0.f;
            #pragma unroll
            for (int s = 0; s < 3; s++) {
                const float* g = ghp + (size_t)s * (BB * GG) + (size_t)b * GG;
                hr += __ldcg(&g[j]);
                hz += __ldcg(&g[HH + j]);
                hn += __ldcg(&g[2 * HH + j]);
            }
            float r = 1.f / (1.f + expf(-(ir + hr)));
            float z = 1.f / (1.f + expf(-(iz + hz)));
            float n = tanhf(inn + r * hn);
            float hp = __ldcg(&h[idx]);
            float hnew = (1.f - z) * n + z * hp;
            h[idx] = hnew;
            bf16 hb = __float2bfloat16(hnew);
            bf16 lb = __float2bfloat16(hnew - __bfloat162float(hb));
            size_t ho = (size_t)b * KP1024 + j;
            hhi[ho] = hb;
            hlo[ho] = lb;
            if (seqhi) {
                size_t so = ((size_t)b * TS + t) * KP1024 + j;
                seqhi[so] = hb;
                seqlo[so] = lb;
            }
        }
        __threadfence();
        grid_bar();
    }
}

// ---------------- attention --------------------------------------------------------
__global__ __launch_bounds__(256) void attention_kernel(const float* __restrict__ qkv,
                                                        float* __restrict__ o) {
    extern __shared__ float sm[];
    float* kv = sm;
    float* sc = sm + NF * DHD;
    int b = blockIdx.x >> 2;
    int h = blockIdx.x & 3;
    int tid = threadIdx.x;
    int lane = tid & 31, w = tid >> 5;
    const float* base = qkv + (size_t)b * NF * GG + h * DHD;

    for (int idx = tid; idx < NF * DHD; idx += 256) {
        int t = idx >> 8, d = idx & 255;
        kv[idx] = base[(size_t)t * GG + HH + d];
    }
    __syncthreads();
    for (int i = w; i < NF; i += 8) {
        float q[8];
        const float* qp = base + (size_t)i * GG;
        #pragma unroll
        for (int c = 0; c < 8; c++) q[c] = qp[lane + 32 * c];
        for (int j = 0; j < NF; j++) {
            const float* kp = kv + j * DHD;
            float s = 0.f;
            #pragma unroll
            for (int c = 0; c < 8; c++) s += q[c] * kp[lane + 32 * c];
            #pragma unroll
            for (int off = 16; off; off >>= 1) s += __shfl_xor_sync(0xffffffffu, s, off);
            if (lane == 0) sc[i * 64 + j] = s * 0.0625f;
        }
    }
    __syncthreads();
    for (int i = w; i < NF; i += 8) {
        float v0 = (lane < NF) ? sc[i * 64 + lane] : -1e30f;
        float v1 = (lane + 32 < NF) ? sc[i * 64 + lane + 32] : -1e30f;
        float m = fmaxf(v0, v1);
        #pragma unroll
        for (int off = 16; off; off >>= 1) m = fmaxf(m, __shfl_xor_sync(0xffffffffu, m, off));
        float e0 = (lane < NF) ? expf(v0 - m) : 0.f;
        float e1 = (lane + 32 < NF) ? expf(v1 - m) : 0.f;
        float ss = e0 + e1;
        #pragma unroll
        for (int off = 16; off; off >>= 1) ss += __shfl_xor_sync(0xffffffffu, ss, off);
        float inv = 1.f / ss;
        if (lane < NF) sc[i * 64 + lane] = e0 * inv;
        if (lane + 32 < NF) sc[i * 64 + lane + 32] = e1 * inv;
    }
    __syncthreads();
    for (int idx = tid; idx < NF * DHD; idx += 256) {
        int t = idx >> 8, d = idx & 255;
        kv[idx] = base[(size_t)t * GG + 2 * HH + d];
    }
    __syncthreads();
    float acc[NF];
    #pragma unroll
    for (int i = 0; i < NF; i++) acc[i] = 0.f;
    int d = tid;
    for (int j = 0; j < NF; j++) {
        float vv = kv[j * DHD + d];
        #pragma unroll
        for (int i = 0; i < NF; i++) acc[i] += sc[i * 64 + j] * vv;
    }
    float* ob = o + (size_t)b * NF * HH + h * DHD + d;
    #pragma unroll
    for (int i = 0; i < NF; i++) ob[(size_t)i * HH] = acc[i];
}

__global__ void mean61_kernel(const float* __restrict__ o, float* __restrict__ obar) {
    int idx = blockIdx.x * 256 + threadIdx.x;
    if (idx >= BB * HH) return;
    int b = idx >> 10, c = idx & 1023;
    const float* p = o + (size_t)b * NF * HH + c;
    float s = 0.f;
    for (int t = 0; t < NF; t++) s += p[(size_t)t * HH];
    obar[idx] = s * (1.f / (float)NF);
}

// ---------------- decode gate -------------------------------------------------------
__global__ void gru_gate2(const float* __restrict__ gxp, int gx_sk,
                          const float* __restrict__ ghp, int gh_sk,
                          float* __restrict__ h,
                          bf16* __restrict__ hhi, bf16* __restrict__ hlo) {
    int idx = blockIdx.x * 256 + threadIdx.x;
    if (idx >= BB * HH) return;
    int b = idx >> 10, j = idx & 1023;
    float ir = 0.f, iz = 0.f, in = 0.f;
    for (int s = 0; s < gx_sk; s++) {
        const float* g = gxp + (size_t)s * (BB * GG) + (size_t)b * GG;
        ir += g[j]; iz += g[HH + j]; in += g[2 * HH + j];
    }
    float hr = 0.f, hz = 0.f, hn = 0.f;
    for (int s = 0; s < gh_sk; s++) {
        const float* g = ghp + (size_t)s * (BB * GG) + (size_t)b * GG;
        hr += g[j]; hz += g[HH + j]; hn += g[2 * HH + j];
    }
    float r = 1.f / (1.f + expf(-(ir + hr)));
    float z = 1.f / (1.f + expf(-(iz + hz)));
    float n = tanhf(in + r * hn);
    float hp = h[idx];
    float hnew = (1.f - z) * n + z * hp;
    h[idx] = hnew;
    bf16 hb = __float2bfloat16(hnew);
    size_t ho = (size_t)b * KP1024 + j;
    hhi[ho] = hb;
    hlo[ho] = __float2bfloat16(hnew - __bfloat162float(hb));
}

// ---------------- split-K reductions ------------------------------------------------
__global__ void reduce_act_kernel(const float* __restrict__ part, int sk, int mn,
                                  float* __restrict__ out) {
    int idx = blockIdx.x * 256 + threadIdx.x;
    if (idx >= mn) return;
    float s = 0.f;
    for (int i = 0; i < sk; i++) s += part[(size_t)i * mn + idx];
    out[idx] = fmaxf(s, 0.f);
}

__global__ void reduce_split_kernel(const float* __restrict__ part, int sk,
                                    const float* __restrict__ addend,
                                    bf16* __restrict__ hi, bf16* __restrict__ lo) {
    int idx = blockIdx.x * 256 + threadIdx.x;
    if (idx >= BB * HH) return;
    int b = idx >> 10, j = idx & 1023;
    float s = 0.f;
    for (int i = 0; i < sk; i++) s += part[(size_t)i * (BB * HH) + idx];
    s = fmaxf(s, 0.f) + addend[idx];
    bf16 hb = __float2bfloat16(s);
    size_t o = (size_t)b * KP1024 + j;
    hi[o] = hb;
    lo[o] = __float2bfloat16(s - __bfloat162float(hb));
}

// ---------------- decode init ---------------------------------------------------------
__global__ void init_decode(const float* __restrict__ inseq,
                            bf16* __restrict__ xthi, bf16* __restrict__ xtlo,
                            float* __restrict__ p6) {
    int idx = blockIdx.x * 256 + threadIdx.x;
    if (idx >= BB * KP135) return;
    int b = idx / KP135, d = idx % KP135;
    const float* last = inseq + ((size_t)b * TS + (TS - 1)) * DD;
    float v = 0.f;
    if (d < DD) v = last[d];
    else if (d == DD) v = 1.0f;
    bf16 hb = __float2bfloat16(v);
    xthi[idx] = hb;
    xtlo[idx] = __float2bfloat16(v - __bfloat162float(hb));
    if (d < NJ * 6) {
        int j = d / 6, o = d % 6;
        int src = (o < 3) ? (j * 9 + o * 3) : (j * 9 + (o - 3) * 3 + 1);
        p6[(size_t)b * 90 + d] = last[src];
    }
}

// ---------------- spl head layer2 + rot6d -------------------------------------------
__global__ __launch_bounds__(192) void spl2_rot(const float* __restrict__ z1,
                                                const float* __restrict__ w2,
                                                const float* __restrict__ b2,
                                                float* __restrict__ p6,
                                                bf16* __restrict__ xthi,
                                                bf16* __restrict__ xtlo,
                                                float* __restrict__ out, int step) {
    int bj = blockIdx.x;
    int b = bj / NJ, j = bj % NJ;
    int w = threadIdx.x >> 5, lane = threadIdx.x & 31;
    __shared__ float v6[6];
    const float* zz = z1 + (size_t)b * (NJ * 128) + j * 128;
    const float* ww = w2 + ((size_t)j * 6 + w) * 128;
    float s = 0.f;
    #pragma unroll
    for (int c = 0; c < 4; c++) s += zz[lane + 32 * c] * ww[lane + 32 * c];
    #pragma unroll
    for (int off = 16; off; off >>= 1) s += __shfl_xor_sync(0xffffffffu, s, off);
    if (lane == 0)
        v6[w] = p6[(size_t)b * 90 + j * 6 + w] + s + b2[j * 6 + w];
    __syncthreads();
    if (threadIdx.x < 6) {
        float v = v6[threadIdx.x];
        p6[(size_t)b * 90 + j * 6 + threadIdx.x] = v;
        out[((size_t)b * PREDN + step) * 90 + j * 6 + threadIdx.x] = v;
    }
    if (threadIdx.x == 0) {
        float a1x = v6[0], a2x = v6[1], a1y = v6[2], a2y = v6[3], a1z = v6[4], a2z = v6[5];
        float n1 = fmaxf(sqrtf(a1x*a1x + a1y*a1y + a1z*a1z), 1e-12f);
        float b1x = a1x / n1, b1y = a1y / n1, b1z = a1z / n1;
        float dot = b1x*a2x + b1y*a2y + b1z*a2z;
        float ox = a2x - dot*b1x, oy = a2y - dot*b1y, oz = a2z - dot*b1z;
        float n2 = fmaxf(sqrtf(ox*ox + oy*oy + oz*oz), 1e-12f);
        float b2x = ox / n2, b2y = oy / n2, b2z = oz / n2;
        float b3x = b1y*b2z - b1z*b2y;
        float b3y = b1z*b2x - b1x*b2z;
        float b3z = b1x*b2y - b1y*b2x;
        float rm[9] = { b1x, b2x, b3x, b1y, b2y, b3y, b1z, b2z, b3z };
        size_t base = (size_t)b * KP135 + j * 9;
        #pragma unroll
        for (int c = 0; c < 9; c++) {
            bf16 hb = __float2bfloat16(rm[c]);
            xthi[base + c] = hb;
            xtlo[base + c] = __float2bfloat16(rm[c] - __bfloat162float(hb));
        }
    }
}

// ---------------- host orchestration --------------------------------------------------

static inline void gemm4(const bf16* ahi, const bf16* alo,
                         const bf16* whi, const bf16* wlo,
                         float* C, int M, int N, int KP, int sk) {
    dim3 g(N / 128, M / 128, sk);
    gemm4_kernel<<<g, 256, SMEM_BYTES>>>(ahi, alo, whi, wlo, C, M, N, KP);
}

static inline void gemm4_dual(const bf16* ah0, const bf16* al0,
                              const bf16* wh0, const bf16* wl0, float* c0, int kp0, int sk0,
                              const bf16* ah1, const bf16* al1,
                              const bf16* wh1, const bf16* wl1, float* c1, int kp1, int sk1) {
    dim3 g(GG / 128, BB / 128, sk0 + sk1);
    gemm4_dual_kernel<<<g, 256, SMEM_BYTES>>>(ah0, al0, wh0, wl0, c0, kp0, sk0,
                                              ah1, al1, wh1, wl1, c1, kp1);
}

static inline void splitw(const float* W, const float* bias,
                          bf16* hi, bf16* lo, int N, int K, int KP) {
    size_t n = (size_t)N * KP;
    split_w_kernel<<<(int)((n + 255) / 256), 256>>>(W, bias, hi, lo, N, K, KP);
}

static inline void splita(const float* A, bf16* hi, bf16* lo, int M, int K, int KP) {
    size_t n = (size_t)M * KP;
    split_a_kernel<<<(int)((n + 255) / 256), 256>>>(A, hi, lo, M, K, KP);
}

static inline void zerosplit(bf16* hi, bf16* lo, int M, int K, int KP) {
    size_t n = (size_t)M * KP;
    zero_split_kernel<<<(int)((n + 255) / 256), 256>>>(hi, lo, M, K, KP);
}

static inline void padinit(bf16* hi, bf16* lo, int M, int K, int KP) {
    size_t n = (size_t)M * (KP - K);
    pad_init_kernel<<<(int)((n + 255) / 256), 256>>>(hi, lo, M, K, KP);
}

extern "C" void kernel_launch(void* const* d_in, const int* in_sizes, int n_in,
                              void* d_out, int out_size) {
    const float* poses      = (const float*)d_in[0];
    const float* freq_w     = (const float*)d_in[1];
    const float* freq_b     = (const float*)d_in[2];
    const float* attn_in_w  = (const float*)d_in[3];
    const float* attn_in_b  = (const float*)d_in[4];
    const float* attn_out_w = (const float*)d_in[5];
    const float* attn_out_b = (const float*)d_in[6];
    const float* gru_wih0   = (const float*)d_in[7];
    const float* gru_whh0   = (const float*)d_in[8];
    const float* gru_bih0   = (const float*)d_in[9];
    const float* gru_bhh0   = (const float*)d_in[10];
    const float* gru_wih1   = (const float*)d_in[11];
    const float* gru_whh1   = (const float*)d_in[12];
    const float* gru_bih1   = (const float*)d_in[13];
    const float* gru_bhh1   = (const float*)d_in[14];
    const float* pre_w      = (const float*)d_in[15];
    const float* pre_b      = (const float*)d_in[16];
    const float* spl_w1     = (const float*)d_in[17];
    const float* spl_b1     = (const float*)d_in[18];
    const float* spl_w2     = (const float*)d_in[19];
    const float* spl_b2     = (const float*)d_in[20];
    float* out = (float*)d_out;

    float *pBig, *pSeq, *pIn, *pFrq, *pCos, *pObar, *pMctx, *pH0, *pH1,
          *pGhp, *pGxp, *pPrep, *pSplp, *pZ1, *pP6;
    bf16 *pWhi, *pWlo, *pAhi, *pAlo;
    cudaGetSymbolAddress((void**)&pBig, g_big);
    cudaGetSymbolAddress((void**)&pSeq, g_seq);
    cudaGetSymbolAddress((void**)&pIn,  g_in);
    cudaGetSymbolAddress((void**)&pFrq, g_frq);
    cudaGetSymbolAddress((void**)&pCos, g_cosm);
    cudaGetSymbolAddress((void**)&pObar, g_obar);
    cudaGetSymbolAddress((void**)&pMctx, g_mctx);
    cudaGetSymbolAddress((void**)&pH0, g_h0);
    cudaGetSymbolAddress((void**)&pH1, g_h1);
    cudaGetSymbolAddress((void**)&pGhp, g_ghp);
    cudaGetSymbolAddress((void**)&pGxp, g_gxp);
    cudaGetSymbolAddress((void**)&pPrep, g_prep);
    cudaGetSymbolAddress((void**)&pSplp, g_splp);
    cudaGetSymbolAddress((void**)&pZ1, g_z1);
    cudaGetSymbolAddress((void**)&pP6, g_p6);
    cudaGetSymbolAddress((void**)&pWhi, g_whi);
    cudaGetSymbolAddress((void**)&pWlo, g_wlo);
    cudaGetSymbolAddress((void**)&pAhi, g_ahi);
    cudaGetSymbolAddress((void**)&pAlo, g_alo);

    cudaFuncSetAttribute(gemm4_kernel, cudaFuncAttributeMaxDynamicSharedMemorySize, SMEM_BYTES);
    cudaFuncSetAttribute(gemm4_dual_kernel, cudaFuncAttributeMaxDynamicSharedMemorySize, SMEM_BYTES);
    cudaFuncSetAttribute(gru_persist_kernel, cudaFuncAttributeMaxDynamicSharedMemorySize, SMEM_BYTES);

    float* qkv   = pBig;
    float* attno = pBig + (size_t)BB * NF * GG;
    float* gi    = pBig;
    float* feat  = pSeq;

    const int BF = BB * NF;
    const int BT = BB * TS;

    // ---- one-time weight splits ----
    splitw(attn_in_w, attn_in_b, pWhi + OFF_ATTNIN,  pWlo + OFF_ATTNIN,  GG, HH, KP1024);
    splitw(gru_wih0,  gru_bih0,  pWhi + OFF_WIH0,    pWlo + OFF_WIH0,    GG, DD, KP135);
    splitw(gru_whh0,  gru_bhh0,  pWhi + OFF_WHH0,    pWlo + OFF_WHH0,    GG, HH, KP1024);
    splitw(gru_wih1,  gru_bih1,  pWhi + OFF_WIH1,    pWlo + OFF_WIH1,    GG, HH, KP1024);
    splitw(gru_whh1,  gru_bhh1,  pWhi + OFF_WHH1,    pWlo + OFF_WHH1,    GG, HH, KP1024);
    splitw(freq_w,    freq_b,    pWhi + OFF_FREQ,    pWlo + OFF_FREQ,    HH, DD, KP135);
    splitw(attn_out_w,attn_out_b,pWhi + OFF_ATTNOUT, pWlo + OFF_ATTNOUT, HH, HH, KP1024);
    splitw(pre_w,     pre_b,     pWhi + OFF_PRE,     pWlo + OFF_PRE,     HH, HH, KP1024);
    splitw(spl_w1,    spl_b1,    pWhi + OFF_SPL1,    pWlo + OFF_SPL1,    NJ*128, HH, KP1024);

    // ---- activation split buffer init ----
    padinit(pAhi + OFFA_SEQ, pAlo + OFFA_SEQ, BT, HH, KP1024);
    zerosplit(pAhi + OFFA_H0,  pAlo + OFFA_H0,  BB, HH, KP1024);
    zerosplit(pAhi + OFFA_H1,  pAlo + OFFA_H1,  BB, HH, KP1024);
    padinit(pAhi + OFFA_HID, pAlo + OFFA_HID, BB, HH, KP1024);

    // ---- frequency attention branch ----
    copy_inseq_kernel<<<(BB*TS*DD + 255) / 256, 256>>>(poses, pIn);
    build_cos_kernel<<<(NF*TS + 255) / 256, 256>>>(pCos);
    freq_kernel<<<dim3(BB, NF), 160>>>(pIn, pCos, pFrq);
    splita(pFrq, pAhi + OFFA_FRQ, pAlo + OFFA_FRQ, BF, DD, KP135);
    gemm4(pAhi + OFFA_FRQ, pAlo + OFFA_FRQ, pWhi + OFF_FREQ, pWlo + OFF_FREQ,
          feat, BF, HH, KP135, 1);
    splita(feat, pAhi + OFFA_FEAT, pAlo + OFFA_FEAT, BF, HH, KP1024);
    gemm4(pAhi + OFFA_FEAT, pAlo + OFFA_FEAT, pWhi + OFF_ATTNIN, pWlo + OFF_ATTNIN,
          qkv, BF, GG, KP1024, 1);

    int smem_attn = (NF * DHD + NF * 64) * (int)sizeof(float);
    cudaFuncSetAttribute(attention_kernel, cudaFuncAttributeMaxDynamicSharedMemorySize, smem_attn);
    attention_kernel<<<BB * NHEAD, 256, smem_attn>>>(qkv, attno);
    mean61_kernel<<<(BB*HH + 255) / 256, 256>>>(attno, pObar);
    splita(pObar, pAhi + OFFA_OBAR, pAlo + OFFA_OBAR, BB, HH, KP1024);
    gemm4(pAhi + OFFA_OBAR, pAlo + OFFA_OBAR, pWhi + OFF_ATTNOUT, pWlo + OFF_ATTNOUT,
          pMctx, BB, HH, KP1024, 1);

    // ---- GRU layer 0 (persistent recurrence, R7 streamed form) ----
    splita(pIn, pAhi + OFFA_IN, pAlo + OFFA_IN, BT, DD, KP135);
    gemm4(pAhi + OFFA_IN, pAlo + OFFA_IN, pWhi + OFF_WIH0, pWlo + OFF_WIH0,
          gi, BT, GG, KP135, 1);
    cudaMemsetAsync(pH0, 0, (size_t)BB * HH * sizeof(float));
    gru_persist_kernel<<<NBLK, 256, SMEM_BYTES>>>(gi, pWhi + OFF_WHH0, pWlo + OFF_WHH0,
                                      pH0, pAhi + OFFA_H0, pAlo + OFFA_H0, pGhp,
                                      pAhi + OFFA_SEQ, pAlo + OFFA_SEQ, TS);

    // ---- GRU layer 1 ----
    gemm4(pAhi + OFFA_SEQ, pAlo + OFFA_SEQ, pWhi + OFF_WIH1, pWlo + OFF_WIH1,
          gi, BT, GG, KP1024, 1);
    cudaMemsetAsync(pH1, 0, (size_t)BB * HH * sizeof(float));
    gru_persist_kernel<<<NBLK, 256, SMEM_BYTES>>>(gi, pWhi + OFF_WHH1, pWlo + OFF_WHH1,
                                      pH1, pAhi + OFFA_H1, pAlo + OFFA_H1, pGhp,
                                      nullptr, nullptr, TS);

    // ---- autoregressive decode (dual-GEMM batched pairs) ----
    init_decode<<<(BB*KP135 + 255) / 256, 256>>>(pIn, pAhi + OFFA_XT, pAlo + OFFA_XT, pP6);
    for (int s = 0; s < PREDN; s++) {
        gemm4_dual(pAhi + OFFA_XT, pAlo + OFFA_XT, pWhi + OFF_WIH0, pWlo + OFF_WIH0,
                   pGxp, KP135, 2,
                   pAhi + OFFA_H0, pAlo + OFFA_H0, pWhi + OFF_WHH0, pWlo + OFF_WHH0,
                   pGhp, KP1024, 4);
        gru_gate2<<<(BB*HH)/256, 256>>>(pGxp, 2, pGhp, 4, pH0,
                                        pAhi + OFFA_H0, pAlo + OFFA_H0);

        gemm4_dual(pAhi + OFFA_H0, pAlo + OFFA_H0, pWhi + OFF_WIH1, pWlo + OFF_WIH1,
                   pGxp, KP1024, 4,
                   pAhi + OFFA_H1, pAlo + OFFA_H1, pWhi + OFF_WHH1, pWlo + OFF_WHH1,
                   pGhp, KP1024, 4);
        gru_gate2<<<(BB*HH)/256, 256>>>(pGxp, 4, pGhp, 4, pH1,
                                        pAhi + OFFA_H1, pAlo + OFFA_H1);

        gemm4(pAhi + OFFA_H1, pAlo + OFFA_H1, pWhi + OFF_PRE, pWlo + OFF_PRE,
              pPrep, BB, HH, KP1024, 8);
        reduce_split_kernel<<<(BB*HH + 255)/256, 256>>>(pPrep, 8, pMctx,
                                                        pAhi + OFFA_HID, pAlo + OFFA_HID);

        gemm4(pAhi + OFFA_HID, pAlo + OFFA_HID, pWhi + OFF_SPL1, pWlo + OFF_SPL1,
              pSplp, BB, NJ*128, KP1024, 8);
        reduce_act_kernel<<<(BB*NJ*128 + 255)/256, 256>>>(pSplp, 8, BB*NJ*128, pZ1);

        spl2_rot<<<BB * NJ, 192>>>(pZ1, spl_w2, spl_b2, pP6,
                                   pAhi + OFFA_XT, pAlo + OFFA_XT, out, s);
    }
}